// round 11
// baseline (speedup 1.0000x reference)
#include <cuda_runtime.h>
#include <cuda_bf16.h>
#include <math.h>
#include <stdint.h>

// ---------------- problem constants ----------------
#define D_H 256
#define D_S 552
#define LT  128
#define NB_ 64
#define MAXDEC 1000
#define G4 1024
#define M_ENC (LT*NB_)       // 8192
#define M_DEC (MAXDEC*NB_)   // 64000
#define M_VAL 51200
#define STOP_OFF ((size_t)M_DEC * D_S)
#define KP_S 560
#define NSEG 4
#define SEG_STEPS 250
#define SEG_ROWS  (SEG_STEPS*NB_)   // 16000

// ---------------- device scratch ----------------
__device__ __align__(256) float g_TE[M_ENC * D_H];
__device__ __align__(256) float g_XencG[M_ENC * G4];
__device__ __align__(256) float g_Xd[(size_t)M_VAL * D_H];
__device__ __align__(256) float g_XdG[(size_t)M_VAL * G4];
__device__ __align__(256) float g_H[(size_t)M_DEC * D_H];
__device__ __align__(256) float g_Hid[(size_t)M_DEC * D_H];
__device__ __align__(256) float g_StopP[M_DEC];
__device__ __align__(256) float g_Wr[995328];
__device__ __align__(256) float g_bcat[512];
__device__ __align__(256) float g_cvec[G4];
__device__ float g_hbuf[2 * D_H * NB_];    // global h handoff: [b][j] (first 16384 used)
__device__ float g_cbuf[D_H * NB_];

#define W_ENC   0
#define W_DEC   262144
#define W_PRE   524288
#define W_P1S   667648
#define W_POST2 798720

__device__ __forceinline__ float to_tf32(float x) {
    float r; asm("cvt.rna.tf32.f32 %0, %1;" : "=f"(r) : "f"(x)); return r;
}

// ---------------- fused prep ----------------
#define P_HB  32768
#define P_BC  (P_HB + 512)
#define P_ENC (P_BC + 262144)
#define P_DEC (P_ENC + 262144)
#define P_PRE (P_DEC + 143360)
#define P_W1  (P_PRE + 65536)
#define P_S1  (P_W1 + 65536)
#define P_W2  (P_S1 + 196608)

__global__ void prep_k(const float* __restrict__ encWih, const float* __restrict__ decWih,
                       const float* __restrict__ preW,  const float* __restrict__ postW1,
                       const float* __restrict__ stopW1,const float* __restrict__ postW2,
                       const float* __restrict__ b1,    const float* __restrict__ b2) {
    int idx = blockIdx.x * 256 + threadIdx.x;
    if (idx < P_HB) { g_hbuf[idx] = 0.f; return; }
    if (idx < P_BC) { int i = idx - P_HB; g_bcat[i] = (i < 256) ? b1[i] : b2[i - 256]; return; }
    if (idx < P_ENC){ int i = idx - P_BC; g_Wr[W_ENC + i] = to_tf32(encWih[i]); return; }
    if (idx < P_DEC){ int i = idx - P_ENC; g_Wr[W_DEC + i] = to_tf32(decWih[i]); return; }
    if (idx < P_PRE){ int i = idx - P_DEC; int r = i / KP_S, c = i - r * KP_S;
                      g_Wr[W_PRE + i] = (c < D_S) ? to_tf32(preW[r * D_S + c]) : 0.f; return; }
    if (idx < P_W1) { int i = idx - P_PRE; g_Wr[W_P1S + i] = to_tf32(postW1[i]); return; }
    if (idx < P_S1) { int i = idx - P_W1;  g_Wr[W_P1S + 65536 + i] = to_tf32(stopW1[i]); return; }
    if (idx < P_W2) { int i = idx - P_S1;  int r = i >> 8;
                      g_Wr[W_POST2 + i] = (r < D_S) ? to_tf32(postW2[i]) : 0.f; return; }
}

__global__ void gather_emb(const int* __restrict__ tok, const float* __restrict__ emb,
                           float* __restrict__ te) {
    int r = blockIdx.x;
    int k = threadIdx.x;
    te[r * D_H + k] = to_tf32(emb[tok[r] * D_H + k]);
}

__global__ void cvec_k(const float* __restrict__ pre_b,
                       const float* __restrict__ bih, const float* __restrict__ bhh) {
    int n = blockIdx.x * 8 + (threadIdx.x >> 5);
    int lane = threadIdx.x & 31;
    float acc = 0.f;
#pragma unroll
    for (int k = lane; k < 256; k += 32)
        acc += to_tf32(pre_b[k]) * g_Wr[W_DEC + n * 256 + k];
#pragma unroll
    for (int o = 16; o; o >>= 1) acc += __shfl_down_sync(0xffffffffu, acc, o);
    if (lane == 0) g_cvec[n] = acc + bih[n] + bhh[n];
}

// ---------------- tf32 tensor-core GEMM (unchanged, proven) ----------------
#define BM 128
#define BN 256
#define BK 16
#define SL 20
#define ST_AGES 3
#define AOFF(s) ((s) * (BM * SL))
#define BOFF(s) (ST_AGES * BM * SL + (s) * (BN * SL))
#define GEMM_SMEM (ST_AGES * (BM + BN) * SL * 4)

__device__ __forceinline__ void cp16(uint32_t s, const void* g) {
    asm volatile("cp.async.cg.shared.global [%0], [%1], 16;" :: "r"(s), "l"(g));
}

template<int RA>
__global__ void __launch_bounds__(256, 1) gemm_tc(
    const float* __restrict__ A, int lda, int rowlo, int rowhi, int kvalid,
    const float* __restrict__ B, int ldb,
    const float* __restrict__ bias0, const float* __restrict__ bias1,
    float* __restrict__ C, int M, int N, int K,
    int cmode, int dorelu, int doround,
    const float* __restrict__ w2, float* __restrict__ stopP)
{
    extern __shared__ float smp[];
    __shared__ float spart[4][BM];

    const int tid  = threadIdx.x;
    const int bm   = blockIdx.x * BM;
    const int bn   = blockIdx.y * BN;
    const int warp = tid >> 5, lane = tid & 31;
    const int wm   = (warp & 1) * 64;
    const int wn   = (warp >> 1) * 64;
    const int grp  = lane >> 2;
    const int tig  = lane & 3;

    float acc[4][8][4];
#pragma unroll
    for (int i = 0; i < 4; i++)
#pragma unroll
        for (int j = 0; j < 8; j++)
#pragma unroll
            for (int e = 0; e < 4; e++) acc[i][j][e] = 0.f;

    const int T = K / BK;

#define LOAD_TILE(t)                                                            \
    {                                                                           \
        int k0 = (t) * BK;                                                      \
        int sb = (t) % ST_AGES;                                                 \
        _Pragma("unroll")                                                       \
        for (int i = 0; i < 2; i++) {                                           \
            int f = i * 256 + tid, row = f >> 2, seg = (f & 3) * 4;             \
            int ar = bm + row, kk = k0 + seg;                                   \
            float* da = smp + AOFF(sb) + row * SL + seg;                        \
            if (ar >= rowlo && ar < rowhi && kk < kvalid)                       \
                cp16((uint32_t)__cvta_generic_to_shared(da),                    \
                     A + (size_t)ar * lda + kk);                                \
            else                                                                \
                *(float4*)da = make_float4(0.f, 0.f, 0.f, 0.f);                 \
        }                                                                       \
        _Pragma("unroll")                                                       \
        for (int i = 0; i < 4; i++) {                                           \
            int f = i * 256 + tid, row = f >> 2, seg = (f & 3) * 4;             \
            float* db = smp + BOFF(sb) + row * SL + seg;                        \
            cp16((uint32_t)__cvta_generic_to_shared(db),                        \
                 B + (size_t)(bn + row) * ldb + k0 + seg);                      \
        }                                                                       \
        asm volatile("cp.async.commit_group;" ::: "memory");                    \
    }

    LOAD_TILE(0);
    LOAD_TILE(1);

    for (int t = 0; t < T; t++) {
        asm volatile("cp.async.wait_group 1;" ::: "memory");
        __syncthreads();
        if (t + 2 < T) LOAD_TILE(t + 2);

        const uint32_t* as = reinterpret_cast<const uint32_t*>(smp + AOFF(t % ST_AGES));
        const uint32_t* bs = reinterpret_cast<const uint32_t*>(smp + BOFF(t % ST_AGES));

#pragma unroll
        for (int kk = 0; kk < BK; kk += 8) {
            uint32_t a[4][4], b[8][2];
            const int c0 = kk + tig;
#pragma unroll
            for (int mt = 0; mt < 4; mt++) {
                int r0 = wm + mt * 16 + grp;
                a[mt][0] = as[r0 * SL + c0];
                a[mt][1] = as[(r0 + 8) * SL + c0];
                a[mt][2] = as[r0 * SL + c0 + 4];
                a[mt][3] = as[(r0 + 8) * SL + c0 + 4];
                if (RA) {
#pragma unroll
                    for (int q = 0; q < 4; q++)
                        a[mt][q] = __float_as_uint(to_tf32(__uint_as_float(a[mt][q])));
                }
            }
#pragma unroll
            for (int nt = 0; nt < 8; nt++) {
                int n0 = wn + nt * 8 + grp;
                b[nt][0] = bs[n0 * SL + c0];
                b[nt][1] = bs[n0 * SL + c0 + 4];
            }
#pragma unroll
            for (int mt = 0; mt < 4; mt++)
#pragma unroll
                for (int nt = 0; nt < 8; nt++) {
                    asm volatile(
                        "mma.sync.aligned.m16n8k8.row.col.f32.tf32.tf32.f32 "
                        "{%0,%1,%2,%3}, {%4,%5,%6,%7}, {%8,%9}, {%0,%1,%2,%3};"
                        : "+f"(acc[mt][nt][0]), "+f"(acc[mt][nt][1]),
                          "+f"(acc[mt][nt][2]), "+f"(acc[mt][nt][3])
                        : "r"(a[mt][0]), "r"(a[mt][1]), "r"(a[mt][2]), "r"(a[mt][3]),
                          "r"(b[nt][0]), "r"(b[nt][1]));
                }
        }
        __syncthreads();
    }
#undef LOAD_TILE

    if (cmode == 2 && bn == 256) {
        float myp[4][2];
#pragma unroll
        for (int mt = 0; mt < 4; mt++) { myp[mt][0] = 0.f; myp[mt][1] = 0.f; }
#pragma unroll
        for (int nt = 0; nt < 8; nt++)
#pragma unroll
            for (int e = 0; e < 4; e++) {
                int col = bn + wn + nt * 8 + tig * 2 + (e & 1);
                float wv = __ldg(w2 + (col - 256));
                float bv = __ldg(bias0 + col);
#pragma unroll
                for (int mt = 0; mt < 4; mt++) {
                    float v = fmaxf(acc[mt][nt][e] + bv, 0.f);
                    myp[mt][e >> 1] += v * wv;
                }
            }
#pragma unroll
        for (int mt = 0; mt < 4; mt++)
#pragma unroll
            for (int h = 0; h < 2; h++) {
                float v = myp[mt][h];
                v += __shfl_xor_sync(0xffffffffu, v, 1);
                v += __shfl_xor_sync(0xffffffffu, v, 2);
                myp[mt][h] = v;
            }
        if (tig == 0) {
            int wi = warp >> 1;
#pragma unroll
            for (int mt = 0; mt < 4; mt++)
#pragma unroll
                for (int h = 0; h < 2; h++)
                    spart[wi][wm + mt * 16 + grp + 8 * h] = myp[mt][h];
        }
        __syncthreads();
        if (tid < BM)
            stopP[bm + tid] = spart[0][tid] + spart[1][tid] + spart[2][tid] + spart[3][tid];
        return;
    }

#pragma unroll
    for (int nt = 0; nt < 8; nt++) {
#pragma unroll
        for (int e = 0; e < 4; e++) {
            int col = bn + wn + nt * 8 + tig * 2 + (e & 1);
            if (col >= N) continue;
            float bv = 0.f;
            if (bias0) bv += __ldg(bias0 + col);
            if (bias1) bv += __ldg(bias1 + col);
#pragma unroll
            for (int mt = 0; mt < 4; mt++) {
                int row = bm + wm + mt * 16 + grp + ((e >> 1) << 3);
                float v = acc[mt][nt][e] + bv;
                if (dorelu) v = fmaxf(v, 0.f);
                if (doround) v = to_tf32(v);
                if (cmode == 0)
                    C[(size_t)row * N + col] = v;
                else if (cmode == 1)
                    C[(size_t)(row >> 6) * (64 * (size_t)N) + (size_t)col * 64 + (row & 63)] = v;
                else
                    C[(size_t)row * 256 + col] = v;
            }
        }
    }
}

// ---------------- stop finalize ----------------
__global__ void stopfin_k(const float* __restrict__ b2, float* __restrict__ out) {
    int r = blockIdx.x * 256 + threadIdx.x;
    if (r < M_DEC) out[r] = g_StopP[r] + b2[0];
}

// ---------------- recurrent LSTM: 8 clusters (1 chain each) x 8 CTAs, DSMEM h exchange ----------------
__device__ __forceinline__ float sigmoidf_(float x) { return 1.f / (1.f + __expf(-x)); }

#define CL 8
#define WS_STRIDE 258
#define HB_STRIDE 258
#define WS_FLOATS (128 * WS_STRIDE)            // 33024
#define HB_OFF    WS_FLOATS
#define HB_FLOATS (2 * 8 * HB_STRIDE)          // 4128
#define GA_OFF    (HB_OFF + HB_FLOATS)
#define GA_FLOATS (128 * 9)                    // 1152
#define LSTM_SMEM ((WS_FLOATS + HB_FLOATS + GA_FLOATS) * 4)   // 153216 B

__device__ __forceinline__ void st_cluster_f32(uint32_t addr, uint32_t rank, float v) {
    uint32_t r;
    asm volatile("mapa.shared::cluster.u32 %0, %1, %2;" : "=r"(r) : "r"(addr), "r"(rank));
    asm volatile("st.shared::cluster.f32 [%0], %1;" :: "r"(r), "f"(v) : "memory");
}

// DEC=0: encoder steps [0,LT); DEC=1: decoder steps [s0,s1e)
// cluster c (blk>>3) = batch chain [c*8, c*8+8); rank (blk&7) owns h-cols [rank*32, +32)
template<int DEC>
__global__ void __launch_bounds__(256, 1) __cluster_dims__(CL, 1, 1)
lstm_k(const float* __restrict__ Whh, const int* __restrict__ tlen, int s0, int s1e)
{
    extern __shared__ float sm[];
    float* Ws   = sm;                 // [128][WS_STRIDE] scalar weights (own 128 gate-rows)
    float* hbuf = sm + HB_OFF;        // [2][8][HB_STRIDE] full h (all 256 cols) per batch
    float* gacc = sm + GA_OFF;        // [128][9] full-k dot results

    const int tid   = threadIdx.x;
    const int blk   = blockIdx.x;
    const int chain = blk >> 3;
    const uint32_t rank = (uint32_t)(blk & 7);
    const int b0 = chain * 8;
    const int j0 = (int)rank * 32;

    // weights: rows gl = g*32 + jj (own cols), k-major, padded stride
    for (int idx = tid; idx < 128 * 256; idx += 256) {
        int gl = idx >> 8, k = idx & 255;
        int g = gl >> 5, jj = gl & 31;
        Ws[gl * WS_STRIDE + k] = Whh[(g * 256 + j0 + jj) * 256 + k];
    }
    // initial h: full 8 batches x 256 cols from global [b][j]
    for (int idx = tid; idx < 8 * 256; idx += 256) {
        int bb = idx >> 8, j = idx & 255;
        hbuf[bb * HB_STRIDE + j] = g_hbuf[(b0 + bb) * 256 + j];
    }

    const int row  = tid >> 1;        // 0..127: gate-row for compute phase
    const int half = tid & 1;         // batch half (4 batches each)
    const int jj = tid >> 3;          // output col-in-CTA
    const int bb = tid & 7;           // output batch-in-chain
    const int uj = j0 + jj;
    const int ub = b0 + bb;
    const uint32_t smem_base = (uint32_t)__cvta_generic_to_shared(sm);
    float c_reg = 0.f;
    const int mylen = (DEC == 0) ? tlen[ub] : 0;
    if (DEC == 1 && s0 > LT) c_reg = g_cbuf[uj * 64 + ub];
    __syncthreads();

    for (int s = s0; s < s1e; s++) {
        const int p = (s - s0) & 1;
        const float* hc = hbuf + p * (8 * HB_STRIDE);

        // gvx prefetch (h-independent)
        float gvx[4];
        if (DEC == 1) {
            int t = s - LT;
            if (t < 800) {
#pragma unroll
                for (int g = 0; g < 4; g++)
                    gvx[g] = __ldcg(g_XdG + (size_t)t * ((size_t)G4 * NB_)
                                    + ((g * 256 + uj) << 6) + ub);
            } else {
#pragma unroll
                for (int g = 0; g < 4; g++)
                    gvx[g] = __ldg(g_cvec + g * 256 + uj);
            }
        } else {
#pragma unroll
            for (int g = 0; g < 4; g++)
                gvx[g] = __ldcg(g_XencG + (size_t)s * (G4 * NB_)
                                + ((g * 256 + uj) << 6) + ub);
        }

        // compute: full-k dot for (row, 4 batches) via k-pair f32x2
        {
            unsigned long long a0 = 0ull, a1 = 0ull, a2 = 0ull, a3 = 0ull;
            const float* Wr = Ws + row * WS_STRIDE;
            const float* hB = hc + half * 4 * HB_STRIDE;
#pragma unroll 4
            for (int kp = 0; kp < 128; kp++) {
                unsigned long long w = *(const unsigned long long*)(Wr + 2 * kp);
                unsigned long long h0 = *(const unsigned long long*)(hB + 0 * HB_STRIDE + 2 * kp);
                unsigned long long h1 = *(const unsigned long long*)(hB + 1 * HB_STRIDE + 2 * kp);
                unsigned long long h2_ = *(const unsigned long long*)(hB + 2 * HB_STRIDE + 2 * kp);
                unsigned long long h3 = *(const unsigned long long*)(hB + 3 * HB_STRIDE + 2 * kp);
                asm("fma.rn.f32x2 %0, %1, %2, %0;" : "+l"(a0) : "l"(h0), "l"(w));
                asm("fma.rn.f32x2 %0, %1, %2, %0;" : "+l"(a1) : "l"(h1), "l"(w));
                asm("fma.rn.f32x2 %0, %1, %2, %0;" : "+l"(a2) : "l"(h2_), "l"(w));
                asm("fma.rn.f32x2 %0, %1, %2, %0;" : "+l"(a3) : "l"(h3), "l"(w));
            }
            float2 f0 = *(float2*)&a0, f1 = *(float2*)&a1;
            float2 f2 = *(float2*)&a2, f3 = *(float2*)&a3;
            float* gr = gacc + row * 9 + half * 4;
            gr[0] = f0.x + f0.y; gr[1] = f1.x + f1.y;
            gr[2] = f2.x + f2.y; gr[3] = f3.x + f3.y;
        }
        __syncthreads();

        // update: thread owns (col uj, batch ub)
        float gv0 = gvx[0] + gacc[(0 * 32 + jj) * 9 + bb];
        float gv1 = gvx[1] + gacc[(1 * 32 + jj) * 9 + bb];
        float gv2 = gvx[2] + gacc[(2 * 32 + jj) * 9 + bb];
        float gv3 = gvx[3] + gacc[(3 * 32 + jj) * 9 + bb];
        if (DEC == 1 && s == LT)
            c_reg = hc[bb * HB_STRIDE + uj];

        float iv = sigmoidf_(gv0);
        float fv = sigmoidf_(gv1);
        float gg = tanhf(gv2);
        float ov = sigmoidf_(gv3);
        float c2 = fv * c_reg + iv * gg;
        float h2 = ov * tanhf(c2);
        float hnew;
        if (DEC == 0) {
            bool m = (s < mylen);
            float hold = hc[bb * HB_STRIDE + uj];
            c_reg = m ? c2 : c_reg;
            hnew  = m ? h2 : hold;
        } else {
            c_reg = c2;
            hnew  = h2;
        }

        // broadcast own h value into every cluster CTA's hbuf[nxt]
        {
            uint32_t dst = smem_base +
                (uint32_t)((HB_OFF + (p ^ 1) * (8 * HB_STRIDE) + bb * HB_STRIDE + uj) * 4);
#pragma unroll
            for (uint32_t r = 0; r < CL; r++)
                st_cluster_f32(dst, r, hnew);
        }
        if (DEC == 1)
            g_H[(size_t)(s - LT) * (NB_ * D_H) + ub * D_H + uj] = to_tf32(hnew);
        if (s == s1e - 1)
            g_hbuf[ub * 256 + uj] = hnew;

        // cluster barrier: orders DSMEM stores (release) before next step's reads (acquire)
        asm volatile("barrier.cluster.arrive.aligned;" ::: "memory");
        asm volatile("barrier.cluster.wait.aligned;" ::: "memory");
    }
    if (DEC == 1) g_cbuf[uj * 64 + ub] = c_reg;
}

// ---------------- launch ----------------
extern "C" void kernel_launch(void* const* d_in, const int* in_sizes, int n_in,
                              void* d_out, int out_size) {
    const int*   token_pad     = (const int*)  d_in[0];
    const int*   token_lengths = (const int*)  d_in[1];
    const float* S_true        = (const float*)d_in[2];
    const float* emb           = (const float*)d_in[3];
    const float* enc_Wih       = (const float*)d_in[4];
    const float* enc_Whh       = (const float*)d_in[5];
    const float* enc_bih       = (const float*)d_in[6];
    const float* enc_bhh       = (const float*)d_in[7];
    const float* dec_Wih       = (const float*)d_in[8];
    const float* dec_Whh       = (const float*)d_in[9];
    const float* dec_bih       = (const float*)d_in[10];
    const float* dec_bhh       = (const float*)d_in[11];
    const float* pre_W         = (const float*)d_in[12];
    const float* pre_b         = (const float*)d_in[13];
    const float* post_W1       = (const float*)d_in[14];
    const float* post_b1       = (const float*)d_in[15];
    const float* post_W2       = (const float*)d_in[16];
    const float* post_b2       = (const float*)d_in[17];
    const float* stop_W1       = (const float*)d_in[18];
    const float* stop_b1       = (const float*)d_in[19];
    const float* stop_W2       = (const float*)d_in[20];
    const float* stop_b2       = (const float*)d_in[21];
    float* out = (float*)d_out;

    float *pTE, *pXencG, *pXd, *pXdG, *pH, *pHid, *pWr, *pStopP, *pBcat;
    cudaGetSymbolAddress((void**)&pTE,    g_TE);
    cudaGetSymbolAddress((void**)&pXencG, g_XencG);
    cudaGetSymbolAddress((void**)&pXd,    g_Xd);
    cudaGetSymbolAddress((void**)&pXdG,   g_XdG);
    cudaGetSymbolAddress((void**)&pH,     g_H);
    cudaGetSymbolAddress((void**)&pHid,   g_Hid);
    cudaGetSymbolAddress((void**)&pWr,    g_Wr);
    cudaGetSymbolAddress((void**)&pStopP, g_StopP);
    cudaGetSymbolAddress((void**)&pBcat,  g_bcat);

    static bool s_init = false;
    static cudaStream_t s1, s2;
    static cudaEvent_t evR, evD, evJ, evL[NSEG];
    if (!s_init) {
        s_init = true;
        cudaStreamCreateWithFlags(&s1, cudaStreamNonBlocking);
        cudaStreamCreateWithFlags(&s2, cudaStreamNonBlocking);
        cudaEventCreateWithFlags(&evR, cudaEventDisableTiming);
        cudaEventCreateWithFlags(&evD, cudaEventDisableTiming);
        cudaEventCreateWithFlags(&evJ, cudaEventDisableTiming);
        for (int i = 0; i < NSEG; i++) cudaEventCreateWithFlags(&evL[i], cudaEventDisableTiming);
        cudaFuncSetAttribute(gemm_tc<0>, cudaFuncAttributeMaxDynamicSharedMemorySize, GEMM_SMEM);
        cudaFuncSetAttribute(gemm_tc<1>, cudaFuncAttributeMaxDynamicSharedMemorySize, GEMM_SMEM);
        cudaFuncSetAttribute(lstm_k<0>,  cudaFuncAttributeMaxDynamicSharedMemorySize, LSTM_SMEM);
        cudaFuncSetAttribute(lstm_k<1>,  cudaFuncAttributeMaxDynamicSharedMemorySize, LSTM_SMEM);
    }

    // ---- stream 0: prep ----
    prep_k<<<(P_W2 + 255) / 256, 256>>>(enc_Wih, dec_Wih, pre_W, post_W1, stop_W1, post_W2,
                                        post_b1, stop_b1);
    gather_emb<<<M_ENC, 256>>>(token_pad, emb, pTE);
    cudaEventRecord(evR, 0);
    gemm_tc<0><<<dim3(M_ENC/128, G4/256), 256, GEMM_SMEM>>>(pTE, 256, 0, M_ENC, 256,
        pWr + W_ENC, 256, enc_bih, enc_bhh, pXencG, M_ENC, G4, 256, 1, 0, 0, nullptr, nullptr);
    lstm_k<0><<<64, 256, LSTM_SMEM>>>(enc_Whh, token_lengths, 0, LT);

    // ---- s1: pre-net + dec-gate + cvec, overlapping the encoder ----
    cudaStreamWaitEvent(s1, evR, 0);
    gemm_tc<1><<<dim3(M_VAL/128, 1), 256, GEMM_SMEM, s1>>>(S_true, D_S, 64, M_VAL, D_S,
        pWr + W_PRE, KP_S, pre_b, nullptr, pXd, M_VAL, D_H, KP_S, 0, 0, 1, nullptr, nullptr);
    gemm_tc<0><<<dim3(M_VAL/128, G4/256), 256, GEMM_SMEM, s1>>>(pXd, 256, 0, M_VAL, 256,
        pWr + W_DEC, 256, dec_bih, dec_bhh, pXdG, M_VAL, G4, 256, 1, 0, 0, nullptr, nullptr);
    cvec_k<<<G4/8, 256, 0, s1>>>(pre_b, dec_bih, dec_bhh);
    cudaEventRecord(evD, s1);

    // ---- stream 0: decoder recurrence in segments ----
    cudaStreamWaitEvent(0, evD, 0);
    for (int i = 0; i < NSEG; i++) {
        lstm_k<1><<<64, 256, LSTM_SMEM>>>(dec_Whh, token_lengths,
                                          LT + i * SEG_STEPS, LT + (i + 1) * SEG_STEPS);
        cudaEventRecord(evL[i], 0);
    }

    // ---- s2: per-segment post-net chunks overlap the decoder recurrence ----
    for (int i = 0; i < NSEG; i++) {
        cudaStreamWaitEvent(s2, evL[i], 0);
        const float* Hc  = pH   + (size_t)SEG_ROWS * i * 256;
        float*       Hic = pHid + (size_t)SEG_ROWS * i * 256;
        gemm_tc<0><<<dim3(SEG_ROWS/128, 2), 256, GEMM_SMEM, s2>>>(Hc, 256, 0, SEG_ROWS, 256,
            pWr + W_P1S, 256, pBcat, nullptr, Hic, SEG_ROWS, 512, 256, 2, 1, 1,
            stop_W2, pStopP + (size_t)SEG_ROWS * i);
        gemm_tc<0><<<dim3(SEG_ROWS/128, 3), 256, GEMM_SMEM, s2>>>(Hic, 256, 0, SEG_ROWS, 256,
            pWr + W_POST2, 256, post_b2, nullptr, out + (size_t)SEG_ROWS * i * D_S,
            SEG_ROWS, D_S, 256, 0, 0, 0, nullptr, nullptr);
    }
    stopfin_k<<<(M_DEC+255)/256, 256, 0, s2>>>(stop_b2, out + STOP_OFF);
    cudaEventRecord(evJ, s2);

    cudaStreamWaitEvent(0, evJ, 0);
}

// round 12
// speedup vs baseline: 1.0619x; 1.0619x over previous
#include <cuda_runtime.h>
#include <cuda_bf16.h>
#include <math.h>
#include <stdint.h>

// ---------------- problem constants ----------------
#define D_H 256
#define D_S 552
#define LT  128
#define NB_ 64
#define MAXDEC 1000
#define G4 1024
#define M_ENC (LT*NB_)       // 8192
#define M_DEC (MAXDEC*NB_)   // 64000
#define M_VAL 51200
#define STOP_OFF ((size_t)M_DEC * D_S)
#define KP_S 560
#define NSEG 4
#define SEG_STEPS 250
#define SEG_ROWS  (SEG_STEPS*NB_)   // 16000

// ---------------- device scratch ----------------
__device__ __align__(256) float g_TE[M_ENC * D_H];
__device__ __align__(256) float g_XencG[M_ENC * G4];
__device__ __align__(256) float g_Xd[(size_t)M_VAL * D_H];
__device__ __align__(256) float g_XdG[(size_t)M_VAL * G4];
__device__ __align__(256) float g_H[(size_t)M_DEC * D_H];
__device__ __align__(256) float g_Hid[(size_t)M_DEC * D_H];
__device__ __align__(256) float g_StopP[M_DEC];
__device__ __align__(256) float g_Wr[995328];
__device__ __align__(256) float g_bcat[512];
__device__ __align__(256) float g_cvec[G4];
__device__ float g_hbuf[2 * D_H * NB_];    // global h handoff: [b][j]
__device__ float g_cbuf[D_H * NB_];

#define W_ENC   0
#define W_DEC   262144
#define W_PRE   524288
#define W_P1S   667648
#define W_POST2 798720

__device__ __forceinline__ float to_tf32(float x) {
    float r; asm("cvt.rna.tf32.f32 %0, %1;" : "=f"(r) : "f"(x)); return r;
}

// ---------------- fused prep ----------------
#define P_HB  32768
#define P_BC  (P_HB + 512)
#define P_ENC (P_BC + 262144)
#define P_DEC (P_ENC + 262144)
#define P_PRE (P_DEC + 143360)
#define P_W1  (P_PRE + 65536)
#define P_S1  (P_W1 + 65536)
#define P_W2  (P_S1 + 196608)

__global__ void prep_k(const float* __restrict__ encWih, const float* __restrict__ decWih,
                       const float* __restrict__ preW,  const float* __restrict__ postW1,
                       const float* __restrict__ stopW1,const float* __restrict__ postW2,
                       const float* __restrict__ b1,    const float* __restrict__ b2) {
    int idx = blockIdx.x * 256 + threadIdx.x;
    if (idx < P_HB) { g_hbuf[idx] = 0.f; return; }
    if (idx < P_BC) { int i = idx - P_HB; g_bcat[i] = (i < 256) ? b1[i] : b2[i - 256]; return; }
    if (idx < P_ENC){ int i = idx - P_BC; g_Wr[W_ENC + i] = to_tf32(encWih[i]); return; }
    if (idx < P_DEC){ int i = idx - P_ENC; g_Wr[W_DEC + i] = to_tf32(decWih[i]); return; }
    if (idx < P_PRE){ int i = idx - P_DEC; int r = i / KP_S, c = i - r * KP_S;
                      g_Wr[W_PRE + i] = (c < D_S) ? to_tf32(preW[r * D_S + c]) : 0.f; return; }
    if (idx < P_W1) { int i = idx - P_PRE; g_Wr[W_P1S + i] = to_tf32(postW1[i]); return; }
    if (idx < P_S1) { int i = idx - P_W1;  g_Wr[W_P1S + 65536 + i] = to_tf32(stopW1[i]); return; }
    if (idx < P_W2) { int i = idx - P_S1;  int r = i >> 8;
                      g_Wr[W_POST2 + i] = (r < D_S) ? to_tf32(postW2[i]) : 0.f; return; }
}

__global__ void gather_emb(const int* __restrict__ tok, const float* __restrict__ emb,
                           float* __restrict__ te) {
    int r = blockIdx.x;
    int k = threadIdx.x;
    te[r * D_H + k] = to_tf32(emb[tok[r] * D_H + k]);
}

__global__ void cvec_k(const float* __restrict__ pre_b,
                       const float* __restrict__ bih, const float* __restrict__ bhh) {
    int n = blockIdx.x * 8 + (threadIdx.x >> 5);
    int lane = threadIdx.x & 31;
    float acc = 0.f;
#pragma unroll
    for (int k = lane; k < 256; k += 32)
        acc += to_tf32(pre_b[k]) * g_Wr[W_DEC + n * 256 + k];
#pragma unroll
    for (int o = 16; o; o >>= 1) acc += __shfl_down_sync(0xffffffffu, acc, o);
    if (lane == 0) g_cvec[n] = acc + bih[n] + bhh[n];
}

// ---------------- tf32 tensor-core GEMM (unchanged, proven) ----------------
#define BM 128
#define BN 256
#define BK 16
#define SL 20
#define ST_AGES 3
#define AOFF(s) ((s) * (BM * SL))
#define BOFF(s) (ST_AGES * BM * SL + (s) * (BN * SL))
#define GEMM_SMEM (ST_AGES * (BM + BN) * SL * 4)

__device__ __forceinline__ void cp16(uint32_t s, const void* g) {
    asm volatile("cp.async.cg.shared.global [%0], [%1], 16;" :: "r"(s), "l"(g));
}

template<int RA>
__global__ void __launch_bounds__(256, 1) gemm_tc(
    const float* __restrict__ A, int lda, int rowlo, int rowhi, int kvalid,
    const float* __restrict__ B, int ldb,
    const float* __restrict__ bias0, const float* __restrict__ bias1,
    float* __restrict__ C, int M, int N, int K,
    int cmode, int dorelu, int doround,
    const float* __restrict__ w2, float* __restrict__ stopP)
{
    extern __shared__ float smp[];
    __shared__ float spart[4][BM];

    const int tid  = threadIdx.x;
    const int bm   = blockIdx.x * BM;
    const int bn   = blockIdx.y * BN;
    const int warp = tid >> 5, lane = tid & 31;
    const int wm   = (warp & 1) * 64;
    const int wn   = (warp >> 1) * 64;
    const int grp  = lane >> 2;
    const int tig  = lane & 3;

    float acc[4][8][4];
#pragma unroll
    for (int i = 0; i < 4; i++)
#pragma unroll
        for (int j = 0; j < 8; j++)
#pragma unroll
            for (int e = 0; e < 4; e++) acc[i][j][e] = 0.f;

    const int T = K / BK;

#define LOAD_TILE(t)                                                            \
    {                                                                           \
        int k0 = (t) * BK;                                                      \
        int sb = (t) % ST_AGES;                                                 \
        _Pragma("unroll")                                                       \
        for (int i = 0; i < 2; i++) {                                           \
            int f = i * 256 + tid, row = f >> 2, seg = (f & 3) * 4;             \
            int ar = bm + row, kk = k0 + seg;                                   \
            float* da = smp + AOFF(sb) + row * SL + seg;                        \
            if (ar >= rowlo && ar < rowhi && kk < kvalid)                       \
                cp16((uint32_t)__cvta_generic_to_shared(da),                    \
                     A + (size_t)ar * lda + kk);                                \
            else                                                                \
                *(float4*)da = make_float4(0.f, 0.f, 0.f, 0.f);                 \
        }                                                                       \
        _Pragma("unroll")                                                       \
        for (int i = 0; i < 4; i++) {                                           \
            int f = i * 256 + tid, row = f >> 2, seg = (f & 3) * 4;             \
            float* db = smp + BOFF(sb) + row * SL + seg;                        \
            cp16((uint32_t)__cvta_generic_to_shared(db),                        \
                 B + (size_t)(bn + row) * ldb + k0 + seg);                      \
        }                                                                       \
        asm volatile("cp.async.commit_group;" ::: "memory");                    \
    }

    LOAD_TILE(0);
    LOAD_TILE(1);

    for (int t = 0; t < T; t++) {
        asm volatile("cp.async.wait_group 1;" ::: "memory");
        __syncthreads();
        if (t + 2 < T) LOAD_TILE(t + 2);

        const uint32_t* as = reinterpret_cast<const uint32_t*>(smp + AOFF(t % ST_AGES));
        const uint32_t* bs = reinterpret_cast<const uint32_t*>(smp + BOFF(t % ST_AGES));

#pragma unroll
        for (int kk = 0; kk < BK; kk += 8) {
            uint32_t a[4][4], b[8][2];
            const int c0 = kk + tig;
#pragma unroll
            for (int mt = 0; mt < 4; mt++) {
                int r0 = wm + mt * 16 + grp;
                a[mt][0] = as[r0 * SL + c0];
                a[mt][1] = as[(r0 + 8) * SL + c0];
                a[mt][2] = as[r0 * SL + c0 + 4];
                a[mt][3] = as[(r0 + 8) * SL + c0 + 4];
                if (RA) {
#pragma unroll
                    for (int q = 0; q < 4; q++)
                        a[mt][q] = __float_as_uint(to_tf32(__uint_as_float(a[mt][q])));
                }
            }
#pragma unroll
            for (int nt = 0; nt < 8; nt++) {
                int n0 = wn + nt * 8 + grp;
                b[nt][0] = bs[n0 * SL + c0];
                b[nt][1] = bs[n0 * SL + c0 + 4];
            }
#pragma unroll
            for (int mt = 0; mt < 4; mt++)
#pragma unroll
                for (int nt = 0; nt < 8; nt++) {
                    asm volatile(
                        "mma.sync.aligned.m16n8k8.row.col.f32.tf32.tf32.f32 "
                        "{%0,%1,%2,%3}, {%4,%5,%6,%7}, {%8,%9}, {%0,%1,%2,%3};"
                        : "+f"(acc[mt][nt][0]), "+f"(acc[mt][nt][1]),
                          "+f"(acc[mt][nt][2]), "+f"(acc[mt][nt][3])
                        : "r"(a[mt][0]), "r"(a[mt][1]), "r"(a[mt][2]), "r"(a[mt][3]),
                          "r"(b[nt][0]), "r"(b[nt][1]));
                }
        }
        __syncthreads();
    }
#undef LOAD_TILE

    if (cmode == 2 && bn == 256) {
        float myp[4][2];
#pragma unroll
        for (int mt = 0; mt < 4; mt++) { myp[mt][0] = 0.f; myp[mt][1] = 0.f; }
#pragma unroll
        for (int nt = 0; nt < 8; nt++)
#pragma unroll
            for (int e = 0; e < 4; e++) {
                int col = bn + wn + nt * 8 + tig * 2 + (e & 1);
                float wv = __ldg(w2 + (col - 256));
                float bv = __ldg(bias0 + col);
#pragma unroll
                for (int mt = 0; mt < 4; mt++) {
                    float v = fmaxf(acc[mt][nt][e] + bv, 0.f);
                    myp[mt][e >> 1] += v * wv;
                }
            }
#pragma unroll
        for (int mt = 0; mt < 4; mt++)
#pragma unroll
            for (int h = 0; h < 2; h++) {
                float v = myp[mt][h];
                v += __shfl_xor_sync(0xffffffffu, v, 1);
                v += __shfl_xor_sync(0xffffffffu, v, 2);
                myp[mt][h] = v;
            }
        if (tig == 0) {
            int wi = warp >> 1;
#pragma unroll
            for (int mt = 0; mt < 4; mt++)
#pragma unroll
                for (int h = 0; h < 2; h++)
                    spart[wi][wm + mt * 16 + grp + 8 * h] = myp[mt][h];
        }
        __syncthreads();
        if (tid < BM)
            stopP[bm + tid] = spart[0][tid] + spart[1][tid] + spart[2][tid] + spart[3][tid];
        return;
    }

#pragma unroll
    for (int nt = 0; nt < 8; nt++) {
#pragma unroll
        for (int e = 0; e < 4; e++) {
            int col = bn + wn + nt * 8 + tig * 2 + (e & 1);
            if (col >= N) continue;
            float bv = 0.f;
            if (bias0) bv += __ldg(bias0 + col);
            if (bias1) bv += __ldg(bias1 + col);
#pragma unroll
            for (int mt = 0; mt < 4; mt++) {
                int row = bm + wm + mt * 16 + grp + ((e >> 1) << 3);
                float v = acc[mt][nt][e] + bv;
                if (dorelu) v = fmaxf(v, 0.f);
                if (doround) v = to_tf32(v);
                if (cmode == 0)
                    C[(size_t)row * N + col] = v;
                else if (cmode == 1)
                    C[(size_t)(row >> 6) * (64 * (size_t)N) + (size_t)col * 64 + (row & 63)] = v;
                else
                    C[(size_t)row * 256 + col] = v;
            }
        }
    }
}

// ---------------- stop finalize ----------------
__global__ void stopfin_k(const float* __restrict__ b2, float* __restrict__ out) {
    int r = blockIdx.x * 256 + threadIdx.x;
    if (r < M_DEC) out[r] = g_StopP[r] + b2[0];
}

// ---------------- recurrent LSTM: clusters + weights-in-registers ----------------
__device__ __forceinline__ float sigmoidf_(float x) { return 1.f / (1.f + __expf(-x)); }

#define CL 8
#define HB_STRIDE 258
#define HB_FLOATS (2 * 8 * HB_STRIDE)          // 4128
#define GA_OFF    HB_FLOATS
#define GA_STR    132
#define GA_FLOATS (8 * 8 * GA_STR)             // 8448
#define LSTM_SMEM ((HB_FLOATS + GA_FLOATS) * 4)   // 50304 B

__device__ __forceinline__ void st_cluster_f32(uint32_t addr, uint32_t rank, float v) {
    uint32_t r;
    asm volatile("mapa.shared::cluster.u32 %0, %1, %2;" : "=r"(r) : "r"(addr), "r"(rank));
    asm volatile("st.shared::cluster.f32 [%0], %1;" :: "r"(r), "f"(v) : "memory");
}

// cluster c (blk>>3) = batch chain [c*8, +8); rank (blk&7) owns h-cols [rank*32, +32)
// lane owns gate-rows gl = lane*4..lane*4+4 for its warp's k-slice; weights live in registers.
template<int DEC>
__global__ void __launch_bounds__(256, 1) __cluster_dims__(CL, 1, 1)
lstm_k(const float* __restrict__ Whh, const int* __restrict__ tlen, int s0, int s1e)
{
    extern __shared__ float sm[];
    float* hbuf = sm;                 // [2][8][HB_STRIDE] full h per batch
    float* gacc = sm + GA_OFF;        // [8 b][8 warp][GA_STR] partials

    const int tid   = threadIdx.x;
    const int blk   = blockIdx.x;
    const int chain = blk >> 3;
    const uint32_t rank = (uint32_t)(blk & 7);
    const int b0 = chain * 8;
    const int j0 = (int)rank * 32;
    const int warp = tid >> 5, lane = tid & 31;
    const int kp0  = warp * 16;       // this warp's 16 k-pairs (k = 2*kp)

    // one-time: weights into registers. wreg[i][j] = Whh[row(l,i)][2*(kp0+j) .. +1]
    unsigned long long wreg[4][16];
#pragma unroll
    for (int i = 0; i < 4; i++) {
        int gl = lane * 4 + i;
        int grow = (gl >> 5) * 256 + j0 + (gl & 31);
        const float* wp = Whh + (size_t)grow * 256 + 2 * kp0;
#pragma unroll
        for (int j = 0; j < 16; j++)
            wreg[i][j] = *(const unsigned long long*)(wp + 2 * j);
    }

    // initial h
    for (int idx = tid; idx < 8 * 256; idx += 256) {
        int bb = idx >> 8, j = idx & 255;
        hbuf[bb * HB_STRIDE + j] = g_hbuf[(b0 + bb) * 256 + j];
    }

    const int jj = tid >> 3;          // update: output col-in-CTA (0..31)
    const int bb = tid & 7;           // update: batch-in-chain
    const int uj = j0 + jj;
    const int ub = b0 + bb;
    const uint32_t smem_base = (uint32_t)__cvta_generic_to_shared(sm);
    float c_reg = 0.f;
    const int mylen = (DEC == 0) ? tlen[ub] : 0;
    if (DEC == 1 && s0 > LT) c_reg = g_cbuf[uj * 64 + ub];
    __syncthreads();

    for (int s = s0; s < s1e; s++) {
        const int p = (s - s0) & 1;
        const float* hc = hbuf + p * (8 * HB_STRIDE);

        // gvx prefetch (h-independent)
        float gvx[4];
        if (DEC == 1) {
            int t = s - LT;
            if (t < 800) {
#pragma unroll
                for (int g = 0; g < 4; g++)
                    gvx[g] = __ldcg(g_XdG + (size_t)t * ((size_t)G4 * NB_)
                                    + ((g * 256 + uj) << 6) + ub);
            } else {
#pragma unroll
                for (int g = 0; g < 4; g++)
                    gvx[g] = __ldg(g_cvec + g * 256 + uj);
            }
        } else {
#pragma unroll
            for (int g = 0; g < 4; g++)
                gvx[g] = __ldcg(g_XencG + (size_t)s * (G4 * NB_)
                                + ((g * 256 + uj) << 6) + ub);
        }

        // compute: for each batch, 16 broadcast h loads + 64 FFMA2 into 4 accs
#pragma unroll
        for (int b = 0; b < 8; b++) {
            const float* hB = hc + b * HB_STRIDE + 2 * kp0;
            unsigned long long a0 = 0ull, a1 = 0ull, a2 = 0ull, a3 = 0ull;
#pragma unroll
            for (int j = 0; j < 16; j++) {
                unsigned long long hh = *(const unsigned long long*)(hB + 2 * j);
                asm("fma.rn.f32x2 %0, %1, %2, %0;" : "+l"(a0) : "l"(hh), "l"(wreg[0][j]));
                asm("fma.rn.f32x2 %0, %1, %2, %0;" : "+l"(a1) : "l"(hh), "l"(wreg[1][j]));
                asm("fma.rn.f32x2 %0, %1, %2, %0;" : "+l"(a2) : "l"(hh), "l"(wreg[2][j]));
                asm("fma.rn.f32x2 %0, %1, %2, %0;" : "+l"(a3) : "l"(hh), "l"(wreg[3][j]));
            }
            float2 f0 = *(float2*)&a0, f1 = *(float2*)&a1;
            float2 f2 = *(float2*)&a2, f3 = *(float2*)&a3;
            float4 r = make_float4(f0.x + f0.y, f1.x + f1.y, f2.x + f2.y, f3.x + f3.y);
            *(float4*)&gacc[(b * 8 + warp) * GA_STR + 4 * lane] = r;
        }
        __syncthreads();

        // update: thread owns (col uj, batch bb); ordered 8-warp reduction
        float gv[4];
#pragma unroll
        for (int g = 0; g < 4; g++) {
            int gl = g * 32 + jj;
            float v = gvx[g];
#pragma unroll
            for (int w = 0; w < 8; w++) v += gacc[(bb * 8 + w) * GA_STR + gl];
            gv[g] = v;
        }
        if (DEC == 1 && s == LT)
            c_reg = hc[bb * HB_STRIDE + uj];

        float iv = sigmoidf_(gv[0]);
        float fv = sigmoidf_(gv[1]);
        float gg = tanhf(gv[2]);
        float ov = sigmoidf_(gv[3]);
        float c2 = fv * c_reg + iv * gg;
        float h2 = ov * tanhf(c2);
        float hnew;
        if (DEC == 0) {
            bool m = (s < mylen);
            float hold = hc[bb * HB_STRIDE + uj];
            c_reg = m ? c2 : c_reg;
            hnew  = m ? h2 : hold;
        } else {
            c_reg = c2;
            hnew  = h2;
        }

        // broadcast own h value into every cluster CTA's hbuf[nxt]
        {
            uint32_t dst = smem_base +
                (uint32_t)(((p ^ 1) * (8 * HB_STRIDE) + bb * HB_STRIDE + uj) * 4);
#pragma unroll
            for (uint32_t r = 0; r < CL; r++)
                st_cluster_f32(dst, r, hnew);
        }
        if (DEC == 1)
            g_H[(size_t)(s - LT) * (NB_ * D_H) + ub * D_H + uj] = to_tf32(hnew);
        if (s == s1e - 1)
            g_hbuf[ub * 256 + uj] = hnew;

        asm volatile("barrier.cluster.arrive.aligned;" ::: "memory");
        asm volatile("barrier.cluster.wait.aligned;" ::: "memory");
    }
    if (DEC == 1) g_cbuf[uj * 64 + ub] = c_reg;
}

// ---------------- launch ----------------
extern "C" void kernel_launch(void* const* d_in, const int* in_sizes, int n_in,
                              void* d_out, int out_size) {
    const int*   token_pad     = (const int*)  d_in[0];
    const int*   token_lengths = (const int*)  d_in[1];
    const float* S_true        = (const float*)d_in[2];
    const float* emb           = (const float*)d_in[3];
    const float* enc_Wih       = (const float*)d_in[4];
    const float* enc_Whh       = (const float*)d_in[5];
    const float* enc_bih       = (const float*)d_in[6];
    const float* enc_bhh       = (const float*)d_in[7];
    const float* dec_Wih       = (const float*)d_in[8];
    const float* dec_Whh       = (const float*)d_in[9];
    const float* dec_bih       = (const float*)d_in[10];
    const float* dec_bhh       = (const float*)d_in[11];
    const float* pre_W         = (const float*)d_in[12];
    const float* pre_b         = (const float*)d_in[13];
    const float* post_W1       = (const float*)d_in[14];
    const float* post_b1       = (const float*)d_in[15];
    const float* post_W2       = (const float*)d_in[16];
    const float* post_b2       = (const float*)d_in[17];
    const float* stop_W1       = (const float*)d_in[18];
    const float* stop_b1       = (const float*)d_in[19];
    const float* stop_W2       = (const float*)d_in[20];
    const float* stop_b2       = (const float*)d_in[21];
    float* out = (float*)d_out;

    float *pTE, *pXencG, *pXd, *pXdG, *pH, *pHid, *pWr, *pStopP, *pBcat;
    cudaGetSymbolAddress((void**)&pTE,    g_TE);
    cudaGetSymbolAddress((void**)&pXencG, g_XencG);
    cudaGetSymbolAddress((void**)&pXd,    g_Xd);
    cudaGetSymbolAddress((void**)&pXdG,   g_XdG);
    cudaGetSymbolAddress((void**)&pH,     g_H);
    cudaGetSymbolAddress((void**)&pHid,   g_Hid);
    cudaGetSymbolAddress((void**)&pWr,    g_Wr);
    cudaGetSymbolAddress((void**)&pStopP, g_StopP);
    cudaGetSymbolAddress((void**)&pBcat,  g_bcat);

    static bool s_init = false;
    static cudaStream_t s1, s2;
    static cudaEvent_t evR, evD, evJ, evL[NSEG];
    if (!s_init) {
        s_init = true;
        cudaStreamCreateWithFlags(&s1, cudaStreamNonBlocking);
        cudaStreamCreateWithFlags(&s2, cudaStreamNonBlocking);
        cudaEventCreateWithFlags(&evR, cudaEventDisableTiming);
        cudaEventCreateWithFlags(&evD, cudaEventDisableTiming);
        cudaEventCreateWithFlags(&evJ, cudaEventDisableTiming);
        for (int i = 0; i < NSEG; i++) cudaEventCreateWithFlags(&evL[i], cudaEventDisableTiming);
        cudaFuncSetAttribute(gemm_tc<0>, cudaFuncAttributeMaxDynamicSharedMemorySize, GEMM_SMEM);
        cudaFuncSetAttribute(gemm_tc<1>, cudaFuncAttributeMaxDynamicSharedMemorySize, GEMM_SMEM);
        cudaFuncSetAttribute(lstm_k<0>,  cudaFuncAttributeMaxDynamicSharedMemorySize, LSTM_SMEM);
        cudaFuncSetAttribute(lstm_k<1>,  cudaFuncAttributeMaxDynamicSharedMemorySize, LSTM_SMEM);
    }

    // ---- stream 0: prep ----
    prep_k<<<(P_W2 + 255) / 256, 256>>>(enc_Wih, dec_Wih, pre_W, post_W1, stop_W1, post_W2,
                                        post_b1, stop_b1);
    gather_emb<<<M_ENC, 256>>>(token_pad, emb, pTE);
    cudaEventRecord(evR, 0);
    gemm_tc<0><<<dim3(M_ENC/128, G4/256), 256, GEMM_SMEM>>>(pTE, 256, 0, M_ENC, 256,
        pWr + W_ENC, 256, enc_bih, enc_bhh, pXencG, M_ENC, G4, 256, 1, 0, 0, nullptr, nullptr);
    lstm_k<0><<<64, 256, LSTM_SMEM>>>(enc_Whh, token_lengths, 0, LT);

    // ---- s1: pre-net + dec-gate + cvec, overlapping the encoder ----
    cudaStreamWaitEvent(s1, evR, 0);
    gemm_tc<1><<<dim3(M_VAL/128, 1), 256, GEMM_SMEM, s1>>>(S_true, D_S, 64, M_VAL, D_S,
        pWr + W_PRE, KP_S, pre_b, nullptr, pXd, M_VAL, D_H, KP_S, 0, 0, 1, nullptr, nullptr);
    gemm_tc<0><<<dim3(M_VAL/128, G4/256), 256, GEMM_SMEM, s1>>>(pXd, 256, 0, M_VAL, 256,
        pWr + W_DEC, 256, dec_bih, dec_bhh, pXdG, M_VAL, G4, 256, 1, 0, 0, nullptr, nullptr);
    cvec_k<<<G4/8, 256, 0, s1>>>(pre_b, dec_bih, dec_bhh);
    cudaEventRecord(evD, s1);

    // ---- stream 0: decoder recurrence in segments ----
    cudaStreamWaitEvent(0, evD, 0);
    for (int i = 0; i < NSEG; i++) {
        lstm_k<1><<<64, 256, LSTM_SMEM>>>(dec_Whh, token_lengths,
                                          LT + i * SEG_STEPS, LT + (i + 1) * SEG_STEPS);
        cudaEventRecord(evL[i], 0);
    }

    // ---- s2: per-segment post-net chunks overlap the decoder recurrence ----
    for (int i = 0; i < NSEG; i++) {
        cudaStreamWaitEvent(s2, evL[i], 0);
        const float* Hc  = pH   + (size_t)SEG_ROWS * i * 256;
        float*       Hic = pHid + (size_t)SEG_ROWS * i * 256;
        gemm_tc<0><<<dim3(SEG_ROWS/128, 2), 256, GEMM_SMEM, s2>>>(Hc, 256, 0, SEG_ROWS, 256,
            pWr + W_P1S, 256, pBcat, nullptr, Hic, SEG_ROWS, 512, 256, 2, 1, 1,
            stop_W2, pStopP + (size_t)SEG_ROWS * i);
        gemm_tc<0><<<dim3(SEG_ROWS/128, 3), 256, GEMM_SMEM, s2>>>(Hic, 256, 0, SEG_ROWS, 256,
            pWr + W_POST2, 256, post_b2, nullptr, out + (size_t)SEG_ROWS * i * D_S,
            SEG_ROWS, D_S, 256, 0, 0, 0, nullptr, nullptr);
    }
    stopfin_k<<<(M_DEC+255)/256, 256, 0, s2>>>(stop_b2, out + STOP_OFF);
    cudaEventRecord(evJ, s2);

    cudaStreamWaitEvent(0, evJ, 0);
}

// round 13
// speedup vs baseline: 1.1446x; 1.0779x over previous
#include <cuda_runtime.h>
#include <cuda_bf16.h>
#include <math.h>
#include <stdint.h>

// ---------------- problem constants ----------------
#define D_H 256
#define D_S 552
#define LT  128
#define NB_ 64
#define MAXDEC 1000
#define G4 1024
#define M_ENC (LT*NB_)       // 8192
#define M_DEC (MAXDEC*NB_)   // 64000
#define M_VAL 51200
#define STOP_OFF ((size_t)M_DEC * D_S)
#define KP_S 560
#define NSEG 4
#define SEG_STEPS 250
#define SEG_ROWS  (SEG_STEPS*NB_)   // 16000

// ---------------- device scratch ----------------
__device__ __align__(256) float g_TE[M_ENC * D_H];
__device__ __align__(256) float g_XencG[M_ENC * G4];
__device__ __align__(256) float g_Xd[(size_t)M_VAL * D_H];
__device__ __align__(256) float g_XdG[(size_t)M_VAL * G4];
__device__ __align__(256) float g_H[(size_t)M_DEC * D_H];
__device__ __align__(256) float g_Hid[(size_t)M_DEC * D_H];
__device__ __align__(256) float g_StopP[M_DEC];
__device__ __align__(256) float g_Wr[995328];
__device__ __align__(256) float g_bcat[512];
__device__ __align__(256) float g_cvec[G4];
__device__ float g_hbuf[2 * D_H * NB_];    // global h handoff: [b][j]
__device__ float g_cbuf[D_H * NB_];

#define W_ENC   0
#define W_DEC   262144
#define W_PRE   524288
#define W_P1S   667648
#define W_POST2 798720

__device__ __forceinline__ float to_tf32(float x) {
    float r; asm("cvt.rna.tf32.f32 %0, %1;" : "=f"(r) : "f"(x)); return r;
}

// ---------------- fused prep ----------------
#define P_HB  32768
#define P_BC  (P_HB + 512)
#define P_ENC (P_BC + 262144)
#define P_DEC (P_ENC + 262144)
#define P_PRE (P_DEC + 143360)
#define P_W1  (P_PRE + 65536)
#define P_S1  (P_W1 + 65536)
#define P_W2  (P_S1 + 196608)

__global__ void prep_k(const float* __restrict__ encWih, const float* __restrict__ decWih,
                       const float* __restrict__ preW,  const float* __restrict__ postW1,
                       const float* __restrict__ stopW1,const float* __restrict__ postW2,
                       const float* __restrict__ b1,    const float* __restrict__ b2) {
    int idx = blockIdx.x * 256 + threadIdx.x;
    if (idx < P_HB) { g_hbuf[idx] = 0.f; return; }
    if (idx < P_BC) { int i = idx - P_HB; g_bcat[i] = (i < 256) ? b1[i] : b2[i - 256]; return; }
    if (idx < P_ENC){ int i = idx - P_BC; g_Wr[W_ENC + i] = to_tf32(encWih[i]); return; }
    if (idx < P_DEC){ int i = idx - P_ENC; g_Wr[W_DEC + i] = to_tf32(decWih[i]); return; }
    if (idx < P_PRE){ int i = idx - P_DEC; int r = i / KP_S, c = i - r * KP_S;
                      g_Wr[W_PRE + i] = (c < D_S) ? to_tf32(preW[r * D_S + c]) : 0.f; return; }
    if (idx < P_W1) { int i = idx - P_PRE; g_Wr[W_P1S + i] = to_tf32(postW1[i]); return; }
    if (idx < P_S1) { int i = idx - P_W1;  g_Wr[W_P1S + 65536 + i] = to_tf32(stopW1[i]); return; }
    if (idx < P_W2) { int i = idx - P_S1;  int r = i >> 8;
                      g_Wr[W_POST2 + i] = (r < D_S) ? to_tf32(postW2[i]) : 0.f; return; }
}

__global__ void gather_emb(const int* __restrict__ tok, const float* __restrict__ emb,
                           float* __restrict__ te) {
    int r = blockIdx.x;
    int k = threadIdx.x;
    te[r * D_H + k] = to_tf32(emb[tok[r] * D_H + k]);
}

__global__ void cvec_k(const float* __restrict__ pre_b,
                       const float* __restrict__ bih, const float* __restrict__ bhh) {
    int n = blockIdx.x * 8 + (threadIdx.x >> 5);
    int lane = threadIdx.x & 31;
    float acc = 0.f;
#pragma unroll
    for (int k = lane; k < 256; k += 32)
        acc += to_tf32(pre_b[k]) * g_Wr[W_DEC + n * 256 + k];
#pragma unroll
    for (int o = 16; o; o >>= 1) acc += __shfl_down_sync(0xffffffffu, acc, o);
    if (lane == 0) g_cvec[n] = acc + bih[n] + bhh[n];
}

// ---------------- tf32 tensor-core GEMM (unchanged, proven) ----------------
#define BM 128
#define BN 256
#define BK 16
#define SL 20
#define ST_AGES 3
#define AOFF(s) ((s) * (BM * SL))
#define BOFF(s) (ST_AGES * BM * SL + (s) * (BN * SL))
#define GEMM_SMEM (ST_AGES * (BM + BN) * SL * 4)

__device__ __forceinline__ void cp16(uint32_t s, const void* g) {
    asm volatile("cp.async.cg.shared.global [%0], [%1], 16;" :: "r"(s), "l"(g));
}

template<int RA>
__global__ void __launch_bounds__(256, 1) gemm_tc(
    const float* __restrict__ A, int lda, int rowlo, int rowhi, int kvalid,
    const float* __restrict__ B, int ldb,
    const float* __restrict__ bias0, const float* __restrict__ bias1,
    float* __restrict__ C, int M, int N, int K,
    int cmode, int dorelu, int doround,
    const float* __restrict__ w2, float* __restrict__ stopP)
{
    extern __shared__ float smp[];
    __shared__ float spart[4][BM];

    const int tid  = threadIdx.x;
    const int bm   = blockIdx.x * BM;
    const int bn   = blockIdx.y * BN;
    const int warp = tid >> 5, lane = tid & 31;
    const int wm   = (warp & 1) * 64;
    const int wn   = (warp >> 1) * 64;
    const int grp  = lane >> 2;
    const int tig  = lane & 3;

    float acc[4][8][4];
#pragma unroll
    for (int i = 0; i < 4; i++)
#pragma unroll
        for (int j = 0; j < 8; j++)
#pragma unroll
            for (int e = 0; e < 4; e++) acc[i][j][e] = 0.f;

    const int T = K / BK;

#define LOAD_TILE(t)                                                            \
    {                                                                           \
        int k0 = (t) * BK;                                                      \
        int sb = (t) % ST_AGES;                                                 \
        _Pragma("unroll")                                                       \
        for (int i = 0; i < 2; i++) {                                           \
            int f = i * 256 + tid, row = f >> 2, seg = (f & 3) * 4;             \
            int ar = bm + row, kk = k0 + seg;                                   \
            float* da = smp + AOFF(sb) + row * SL + seg;                        \
            if (ar >= rowlo && ar < rowhi && kk < kvalid)                       \
                cp16((uint32_t)__cvta_generic_to_shared(da),                    \
                     A + (size_t)ar * lda + kk);                                \
            else                                                                \
                *(float4*)da = make_float4(0.f, 0.f, 0.f, 0.f);                 \
        }                                                                       \
        _Pragma("unroll")                                                       \
        for (int i = 0; i < 4; i++) {                                           \
            int f = i * 256 + tid, row = f >> 2, seg = (f & 3) * 4;             \
            float* db = smp + BOFF(sb) + row * SL + seg;                        \
            cp16((uint32_t)__cvta_generic_to_shared(db),                        \
                 B + (size_t)(bn + row) * ldb + k0 + seg);                      \
        }                                                                       \
        asm volatile("cp.async.commit_group;" ::: "memory");                    \
    }

    LOAD_TILE(0);
    LOAD_TILE(1);

    for (int t = 0; t < T; t++) {
        asm volatile("cp.async.wait_group 1;" ::: "memory");
        __syncthreads();
        if (t + 2 < T) LOAD_TILE(t + 2);

        const uint32_t* as = reinterpret_cast<const uint32_t*>(smp + AOFF(t % ST_AGES));
        const uint32_t* bs = reinterpret_cast<const uint32_t*>(smp + BOFF(t % ST_AGES));

#pragma unroll
        for (int kk = 0; kk < BK; kk += 8) {
            uint32_t a[4][4], b[8][2];
            const int c0 = kk + tig;
#pragma unroll
            for (int mt = 0; mt < 4; mt++) {
                int r0 = wm + mt * 16 + grp;
                a[mt][0] = as[r0 * SL + c0];
                a[mt][1] = as[(r0 + 8) * SL + c0];
                a[mt][2] = as[r0 * SL + c0 + 4];
                a[mt][3] = as[(r0 + 8) * SL + c0 + 4];
                if (RA) {
#pragma unroll
                    for (int q = 0; q < 4; q++)
                        a[mt][q] = __float_as_uint(to_tf32(__uint_as_float(a[mt][q])));
                }
            }
#pragma unroll
            for (int nt = 0; nt < 8; nt++) {
                int n0 = wn + nt * 8 + grp;
                b[nt][0] = bs[n0 * SL + c0];
                b[nt][1] = bs[n0 * SL + c0 + 4];
            }
#pragma unroll
            for (int mt = 0; mt < 4; mt++)
#pragma unroll
                for (int nt = 0; nt < 8; nt++) {
                    asm volatile(
                        "mma.sync.aligned.m16n8k8.row.col.f32.tf32.tf32.f32 "
                        "{%0,%1,%2,%3}, {%4,%5,%6,%7}, {%8,%9}, {%0,%1,%2,%3};"
                        : "+f"(acc[mt][nt][0]), "+f"(acc[mt][nt][1]),
                          "+f"(acc[mt][nt][2]), "+f"(acc[mt][nt][3])
                        : "r"(a[mt][0]), "r"(a[mt][1]), "r"(a[mt][2]), "r"(a[mt][3]),
                          "r"(b[nt][0]), "r"(b[nt][1]));
                }
        }
        __syncthreads();
    }
#undef LOAD_TILE

    if (cmode == 2 && bn == 256) {
        float myp[4][2];
#pragma unroll
        for (int mt = 0; mt < 4; mt++) { myp[mt][0] = 0.f; myp[mt][1] = 0.f; }
#pragma unroll
        for (int nt = 0; nt < 8; nt++)
#pragma unroll
            for (int e = 0; e < 4; e++) {
                int col = bn + wn + nt * 8 + tig * 2 + (e & 1);
                float wv = __ldg(w2 + (col - 256));
                float bv = __ldg(bias0 + col);
#pragma unroll
                for (int mt = 0; mt < 4; mt++) {
                    float v = fmaxf(acc[mt][nt][e] + bv, 0.f);
                    myp[mt][e >> 1] += v * wv;
                }
            }
#pragma unroll
        for (int mt = 0; mt < 4; mt++)
#pragma unroll
            for (int h = 0; h < 2; h++) {
                float v = myp[mt][h];
                v += __shfl_xor_sync(0xffffffffu, v, 1);
                v += __shfl_xor_sync(0xffffffffu, v, 2);
                myp[mt][h] = v;
            }
        if (tig == 0) {
            int wi = warp >> 1;
#pragma unroll
            for (int mt = 0; mt < 4; mt++)
#pragma unroll
                for (int h = 0; h < 2; h++)
                    spart[wi][wm + mt * 16 + grp + 8 * h] = myp[mt][h];
        }
        __syncthreads();
        if (tid < BM)
            stopP[bm + tid] = spart[0][tid] + spart[1][tid] + spart[2][tid] + spart[3][tid];
        return;
    }

#pragma unroll
    for (int nt = 0; nt < 8; nt++) {
#pragma unroll
        for (int e = 0; e < 4; e++) {
            int col = bn + wn + nt * 8 + tig * 2 + (e & 1);
            if (col >= N) continue;
            float bv = 0.f;
            if (bias0) bv += __ldg(bias0 + col);
            if (bias1) bv += __ldg(bias1 + col);
#pragma unroll
            for (int mt = 0; mt < 4; mt++) {
                int row = bm + wm + mt * 16 + grp + ((e >> 1) << 3);
                float v = acc[mt][nt][e] + bv;
                if (dorelu) v = fmaxf(v, 0.f);
                if (doround) v = to_tf32(v);
                if (cmode == 0)
                    C[(size_t)row * N + col] = v;
                else if (cmode == 1)
                    C[(size_t)(row >> 6) * (64 * (size_t)N) + (size_t)col * 64 + (row & 63)] = v;
                else
                    C[(size_t)row * 256 + col] = v;
            }
        }
    }
}

// ---------------- stop finalize ----------------
__global__ void stopfin_k(const float* __restrict__ b2, float* __restrict__ out) {
    int r = blockIdx.x * 256 + threadIdx.x;
    if (r < M_DEC) out[r] = g_StopP[r] + b2[0];
}

// ---------------- recurrent LSTM: 16 chains x 8-CTA clusters, weights in registers ----------------
__device__ __forceinline__ float sigmoidf_(float x) { return 1.f / (1.f + __expf(-x)); }

#define CL 8
#define CHB 4                                    // batches per chain
#define HB_STRIDE 258
#define HB_FLOATS (2 * CHB * HB_STRIDE)          // 2064
#define GA_OFF    HB_FLOATS
#define GA_STR    132
#define GA_FLOATS (CHB * 8 * GA_STR)             // 4224
#define LSTM_SMEM ((HB_FLOATS + GA_FLOATS) * 4)  // 25152 B

// cluster c (blk>>3) = batch chain [c*4, +4); rank (blk&7) owns h-cols [rank*32, +32)
// lane owns 4 gate-rows for its warp's k-slice; weights live in registers.
template<int DEC>
__global__ void __launch_bounds__(256, 1) __cluster_dims__(CL, 1, 1)
lstm_k(const float* __restrict__ Whh, const int* __restrict__ tlen, int s0, int s1e)
{
    extern __shared__ float sm[];
    float* hbuf = sm;                 // [2][CHB][HB_STRIDE]
    float* gacc = sm + GA_OFF;        // [CHB b][8 warp][GA_STR]

    const int tid   = threadIdx.x;
    const int blk   = blockIdx.x;
    const int chain = blk >> 3;            // 0..15
    const uint32_t rank = (uint32_t)(blk & 7);
    const int b0 = chain * CHB;
    const int j0 = (int)rank * 32;
    const int warp = tid >> 5, lane = tid & 31;
    const int kp0  = warp * 16;

    // one-time: weights into registers (layout identical to R12)
    unsigned long long wreg[4][16];
#pragma unroll
    for (int i = 0; i < 4; i++) {
        int gl = lane * 4 + i;
        int grow = (gl >> 5) * 256 + j0 + (gl & 31);
        const float* wp = Whh + (size_t)grow * 256 + 2 * kp0;
#pragma unroll
        for (int j = 0; j < 16; j++)
            wreg[i][j] = *(const unsigned long long*)(wp + 2 * j);
    }

    // initial h (buffer 0)
    for (int idx = tid; idx < CHB * 256; idx += 256) {
        int bb_ = idx >> 8, j = idx & 255;
        hbuf[bb_ * HB_STRIDE + j] = g_hbuf[(b0 + bb_) * 256 + j];
    }

    const int jj = tid >> 2;          // update: col-in-CTA (0..31)
    const int bb = tid & 3;           // update: batch-in-chain (0..3)
    const int uj = j0 + jj;
    const int ub = b0 + bb;
    const bool upd = (tid < 128);

    // hoisted remote smem bases for broadcast
    const uint32_t smem_base = (uint32_t)__cvta_generic_to_shared(sm);
    uint32_t rbase[CL];
#pragma unroll
    for (int r = 0; r < CL; r++) {
        uint32_t rr;
        asm volatile("mapa.shared::cluster.u32 %0, %1, %2;"
                     : "=r"(rr) : "r"(smem_base), "r"((uint32_t)r));
        rbase[r] = rr;
    }
    const uint32_t off0 = (uint32_t)((0 * (CHB * HB_STRIDE) + bb * HB_STRIDE + uj) * 4);
    const uint32_t off1 = (uint32_t)((1 * (CHB * HB_STRIDE) + bb * HB_STRIDE + uj) * 4);

    float c_reg = 0.f;
    const int mylen = (DEC == 0 && upd) ? tlen[ub] : 0;
    if (DEC == 1 && upd && s0 > LT) c_reg = g_cbuf[uj * 64 + ub];
    __syncthreads();

#define PREF(ss)                                                                  \
    if (upd) {                                                                    \
        if (DEC == 1) {                                                           \
            int t_ = (ss) - LT;                                                   \
            if (t_ < 800) {                                                       \
                _Pragma("unroll")                                                 \
                for (int g = 0; g < 4; g++)                                       \
                    gvx[g] = __ldcg(g_XdG + (size_t)t_ * ((size_t)G4 * NB_)       \
                                    + ((g * 256 + uj) << 6) + ub);                \
            } else {                                                              \
                _Pragma("unroll")                                                 \
                for (int g = 0; g < 4; g++)                                       \
                    gvx[g] = __ldg(g_cvec + g * 256 + uj);                        \
            }                                                                     \
        } else {                                                                  \
            _Pragma("unroll")                                                     \
            for (int g = 0; g < 4; g++)                                           \
                gvx[g] = __ldcg(g_XencG + (size_t)(ss) * (G4 * NB_)               \
                                + ((g * 256 + uj) << 6) + ub);                    \
        }                                                                         \
    }

    float gvx[4];
    PREF(s0);

    for (int s = s0; s < s1e; s++) {
        if (s > s0)
            asm volatile("barrier.cluster.wait.aligned;" ::: "memory");
        const int p = (s - s0) & 1;
        const float* hc = hbuf + p * (CHB * HB_STRIDE);

        // compute: per batch, 16 h LDS.64 + 64 FFMA2 into 4 accumulators
#pragma unroll
        for (int b = 0; b < CHB; b++) {
            const float* hB = hc + b * HB_STRIDE + 2 * kp0;
            unsigned long long a0 = 0ull, a1 = 0ull, a2 = 0ull, a3 = 0ull;
#pragma unroll
            for (int j = 0; j < 16; j++) {
                unsigned long long hh = *(const unsigned long long*)(hB + 2 * j);
                asm("fma.rn.f32x2 %0, %1, %2, %0;" : "+l"(a0) : "l"(hh), "l"(wreg[0][j]));
                asm("fma.rn.f32x2 %0, %1, %2, %0;" : "+l"(a1) : "l"(hh), "l"(wreg[1][j]));
                asm("fma.rn.f32x2 %0, %1, %2, %0;" : "+l"(a2) : "l"(hh), "l"(wreg[2][j]));
                asm("fma.rn.f32x2 %0, %1, %2, %0;" : "+l"(a3) : "l"(hh), "l"(wreg[3][j]));
            }
            float2 f0 = *(float2*)&a0, f1 = *(float2*)&a1;
            float2 f2 = *(float2*)&a2, f3 = *(float2*)&a3;
            float4 r = make_float4(f0.x + f0.y, f1.x + f1.y, f2.x + f2.y, f3.x + f3.y);
            *(float4*)&gacc[(b * 8 + warp) * GA_STR + 4 * lane] = r;
        }
        __syncthreads();

        float hnew = 0.f;
        if (upd) {
            float gv[4];
#pragma unroll
            for (int g = 0; g < 4; g++) {
                int gl = g * 32 + jj;
                float v = gvx[g];
#pragma unroll
                for (int w = 0; w < 8; w++) v += gacc[(bb * 8 + w) * GA_STR + gl];
                gv[g] = v;
            }
            if (DEC == 1 && s == LT)
                c_reg = hc[bb * HB_STRIDE + uj];

            float iv = sigmoidf_(gv[0]);
            float fv = sigmoidf_(gv[1]);
            float gg = tanhf(gv[2]);
            float ov = sigmoidf_(gv[3]);
            float c2 = fv * c_reg + iv * gg;
            float h2 = ov * tanhf(c2);
            if (DEC == 0) {
                bool m = (s < mylen);
                float hold = hc[bb * HB_STRIDE + uj];
                c_reg = m ? c2 : c_reg;
                hnew  = m ? h2 : hold;
            } else {
                c_reg = c2;
                hnew  = h2;
            }
            // broadcast into buffer p^1 of every cluster CTA
            uint32_t off = p ? off0 : off1;
#pragma unroll
            for (int r = 0; r < CL; r++)
                asm volatile("st.shared::cluster.f32 [%0], %1;"
                             :: "r"(rbase[r] + off), "f"(hnew) : "memory");
        }
        asm volatile("barrier.cluster.arrive.aligned;" ::: "memory");

        // off the critical path, between arrive and next wait
        if (DEC == 1 && upd)
            g_H[(size_t)(s - LT) * (NB_ * D_H) + ub * D_H + uj] = to_tf32(hnew);
        if (upd && s == s1e - 1)
            g_hbuf[ub * 256 + uj] = hnew;
        if (s + 1 < s1e) { PREF(s + 1); }
    }
    asm volatile("barrier.cluster.wait.aligned;" ::: "memory");
    if (DEC == 1 && upd) g_cbuf[uj * 64 + ub] = c_reg;
#undef PREF
}

// ---------------- launch ----------------
extern "C" void kernel_launch(void* const* d_in, const int* in_sizes, int n_in,
                              void* d_out, int out_size) {
    const int*   token_pad     = (const int*)  d_in[0];
    const int*   token_lengths = (const int*)  d_in[1];
    const float* S_true        = (const float*)d_in[2];
    const float* emb           = (const float*)d_in[3];
    const float* enc_Wih       = (const float*)d_in[4];
    const float* enc_Whh       = (const float*)d_in[5];
    const float* enc_bih       = (const float*)d_in[6];
    const float* enc_bhh       = (const float*)d_in[7];
    const float* dec_Wih       = (const float*)d_in[8];
    const float* dec_Whh       = (const float*)d_in[9];
    const float* dec_bih       = (const float*)d_in[10];
    const float* dec_bhh       = (const float*)d_in[11];
    const float* pre_W         = (const float*)d_in[12];
    const float* pre_b         = (const float*)d_in[13];
    const float* post_W1       = (const float*)d_in[14];
    const float* post_b1       = (const float*)d_in[15];
    const float* post_W2       = (const float*)d_in[16];
    const float* post_b2       = (const float*)d_in[17];
    const float* stop_W1       = (const float*)d_in[18];
    const float* stop_b1       = (const float*)d_in[19];
    const float* stop_W2       = (const float*)d_in[20];
    const float* stop_b2       = (const float*)d_in[21];
    float* out = (float*)d_out;

    float *pTE, *pXencG, *pXd, *pXdG, *pH, *pHid, *pWr, *pStopP, *pBcat;
    cudaGetSymbolAddress((void**)&pTE,    g_TE);
    cudaGetSymbolAddress((void**)&pXencG, g_XencG);
    cudaGetSymbolAddress((void**)&pXd,    g_Xd);
    cudaGetSymbolAddress((void**)&pXdG,   g_XdG);
    cudaGetSymbolAddress((void**)&pH,     g_H);
    cudaGetSymbolAddress((void**)&pHid,   g_Hid);
    cudaGetSymbolAddress((void**)&pWr,    g_Wr);
    cudaGetSymbolAddress((void**)&pStopP, g_StopP);
    cudaGetSymbolAddress((void**)&pBcat,  g_bcat);

    static bool s_init = false;
    static cudaStream_t s1, s2;
    static cudaEvent_t evR, evJ, evL[NSEG], evDs[NSEG];
    if (!s_init) {
        s_init = true;
        cudaStreamCreateWithFlags(&s1, cudaStreamNonBlocking);
        cudaStreamCreateWithFlags(&s2, cudaStreamNonBlocking);
        cudaEventCreateWithFlags(&evR, cudaEventDisableTiming);
        cudaEventCreateWithFlags(&evJ, cudaEventDisableTiming);
        for (int i = 0; i < NSEG; i++) {
            cudaEventCreateWithFlags(&evL[i],  cudaEventDisableTiming);
            cudaEventCreateWithFlags(&evDs[i], cudaEventDisableTiming);
        }
        cudaFuncSetAttribute(gemm_tc<0>, cudaFuncAttributeMaxDynamicSharedMemorySize, GEMM_SMEM);
        cudaFuncSetAttribute(gemm_tc<1>, cudaFuncAttributeMaxDynamicSharedMemorySize, GEMM_SMEM);
        cudaFuncSetAttribute(lstm_k<0>,  cudaFuncAttributeMaxDynamicSharedMemorySize, LSTM_SMEM);
        cudaFuncSetAttribute(lstm_k<1>,  cudaFuncAttributeMaxDynamicSharedMemorySize, LSTM_SMEM);
    }

    // ---- stream 0: prep + encoder ----
    prep_k<<<(P_W2 + 255) / 256, 256>>>(enc_Wih, dec_Wih, pre_W, post_W1, stop_W1, post_W2,
                                        post_b1, stop_b1);
    gather_emb<<<M_ENC, 256>>>(token_pad, emb, pTE);
    cudaEventRecord(evR, 0);
    gemm_tc<0><<<dim3(M_ENC/128, G4/256), 256, GEMM_SMEM>>>(pTE, 256, 0, M_ENC, 256,
        pWr + W_ENC, 256, enc_bih, enc_bhh, pXencG, M_ENC, G4, 256, 1, 0, 0, nullptr, nullptr);
    lstm_k<0><<<128, 256, LSTM_SMEM>>>(enc_Whh, token_lengths, 0, LT);

    // ---- s1: cvec + 4 pipelined (pre-net, dec-gate) segment chunks ----
    cudaStreamWaitEvent(s1, evR, 0);
    cvec_k<<<G4/8, 256, 0, s1>>>(pre_b, dec_bih, dec_bhh);
    {
        const int rs[NSEG + 1] = {0, 16000, 32000, 48000, M_VAL};
        for (int i = 0; i < NSEG; i++) {
            int r0 = rs[i], Mseg = rs[i + 1] - rs[i];
            gemm_tc<1><<<dim3(Mseg/128, 1), 256, GEMM_SMEM, s1>>>(
                S_true + (size_t)r0 * D_S, D_S, (i == 0 ? 64 : 0), Mseg, D_S,
                pWr + W_PRE, KP_S, pre_b, nullptr, pXd + (size_t)r0 * D_H,
                Mseg, D_H, KP_S, 0, 0, 1, nullptr, nullptr);
            gemm_tc<0><<<dim3(Mseg/128, G4/256), 256, GEMM_SMEM, s1>>>(
                pXd + (size_t)r0 * D_H, 256, 0, Mseg, 256,
                pWr + W_DEC, 256, dec_bih, dec_bhh, pXdG + (size_t)r0 * G4,
                Mseg, G4, 256, 1, 0, 0, nullptr, nullptr);
            cudaEventRecord(evDs[i], s1);
        }
    }

    // ---- stream 0: decoder recurrence, each segment gated on its own gate chunk ----
    for (int i = 0; i < NSEG; i++) {
        cudaStreamWaitEvent(0, evDs[i], 0);
        lstm_k<1><<<128, 256, LSTM_SMEM>>>(dec_Whh, token_lengths,
                                           LT + i * SEG_STEPS, LT + (i + 1) * SEG_STEPS);
        cudaEventRecord(evL[i], 0);
    }

    // ---- s2: per-segment post-net chunks overlap the decoder recurrence ----
    for (int i = 0; i < NSEG; i++) {
        cudaStreamWaitEvent(s2, evL[i], 0);
        const float* Hc  = pH   + (size_t)SEG_ROWS * i * 256;
        float*       Hic = pHid + (size_t)SEG_ROWS * i * 256;
        gemm_tc<0><<<dim3(SEG_ROWS/128, 2), 256, GEMM_SMEM, s2>>>(Hc, 256, 0, SEG_ROWS, 256,
            pWr + W_P1S, 256, pBcat, nullptr, Hic, SEG_ROWS, 512, 256, 2, 1, 1,
            stop_W2, pStopP + (size_t)SEG_ROWS * i);
        gemm_tc<0><<<dim3(SEG_ROWS/128, 3), 256, GEMM_SMEM, s2>>>(Hic, 256, 0, SEG_ROWS, 256,
            pWr + W_POST2, 256, post_b2, nullptr, out + (size_t)SEG_ROWS * i * D_S,
            SEG_ROWS, D_S, 256, 0, 0, 0, nullptr, nullptr);
    }
    stopfin_k<<<(M_DEC+255)/256, 256, 0, s2>>>(stop_b2, out + STOP_OFF);
    cudaEventRecord(evJ, s2);

    cudaStreamWaitEvent(0, evJ, 0);
}

// round 14
// speedup vs baseline: 1.2034x; 1.0514x over previous
#include <cuda_runtime.h>
#include <cuda_bf16.h>
#include <math.h>
#include <stdint.h>

// ---------------- problem constants ----------------
#define D_H 256
#define D_S 552
#define LT  128
#define NB_ 64
#define MAXDEC 1000
#define G4 1024
#define M_ENC (LT*NB_)       // 8192
#define M_DEC (MAXDEC*NB_)   // 64000
#define M_VAL 51200          // rows with non-trivial S_in
#define STOP_OFF ((size_t)M_DEC * D_S)
#define KP_S 560
#define NSEG 4
#define SEG_STEPS 250
#define SEG_ROWS  (SEG_STEPS*NB_)   // 16000

// ---------------- device scratch ----------------
__device__ __align__(256) float g_TE[M_ENC * D_H];
__device__ __align__(256) float g_XencG[M_ENC * G4];
__device__ __align__(256) float g_Xd[(size_t)M_VAL * D_H];
__device__ __align__(256) float g_XdG[(size_t)M_VAL * G4];
__device__ __align__(256) float g_H[(size_t)M_DEC * D_H];
__device__ __align__(256) float g_Hid[(size_t)M_DEC * D_H];
__device__ __align__(256) float g_StopP[M_DEC];
__device__ __align__(256) float g_Wr[995328];
__device__ __align__(256) float g_bcat[512];
__device__ __align__(256) float g_cvec[G4];
__device__ float g_hbuf[2 * D_H * NB_];
__device__ float g_cbuf[D_H * NB_];
__device__ unsigned int g_bar;

#define W_ENC   0
#define W_DEC   262144
#define W_PRE   524288
#define W_P1S   667648
#define W_POST2 798720

__device__ __forceinline__ float to_tf32(float x) {
    float r; asm("cvt.rna.tf32.f32 %0, %1;" : "=f"(r) : "f"(x)); return r;
}

// ---------------- fused prep ----------------
#define P_HB  32768
#define P_BC  (P_HB + 512)
#define P_ENC (P_BC + 262144)
#define P_DEC (P_ENC + 262144)
#define P_PRE (P_DEC + 143360)
#define P_W1  (P_PRE + 65536)
#define P_S1  (P_W1 + 65536)
#define P_W2  (P_S1 + 196608)

__global__ void prep_k(const float* __restrict__ encWih, const float* __restrict__ decWih,
                       const float* __restrict__ preW,  const float* __restrict__ postW1,
                       const float* __restrict__ stopW1,const float* __restrict__ postW2,
                       const float* __restrict__ b1,    const float* __restrict__ b2) {
    int idx = blockIdx.x * 256 + threadIdx.x;
    if (idx == 0) g_bar = 0u;
    if (idx < P_HB) { g_hbuf[idx] = 0.f; return; }
    if (idx < P_BC) { int i = idx - P_HB; g_bcat[i] = (i < 256) ? b1[i] : b2[i - 256]; return; }
    if (idx < P_ENC){ int i = idx - P_BC; g_Wr[W_ENC + i] = to_tf32(encWih[i]); return; }
    if (idx < P_DEC){ int i = idx - P_ENC; g_Wr[W_DEC + i] = to_tf32(decWih[i]); return; }
    if (idx < P_PRE){ int i = idx - P_DEC; int r = i / KP_S, c = i - r * KP_S;
                      g_Wr[W_PRE + i] = (c < D_S) ? to_tf32(preW[r * D_S + c]) : 0.f; return; }
    if (idx < P_W1) { int i = idx - P_PRE; g_Wr[W_P1S + i] = to_tf32(postW1[i]); return; }
    if (idx < P_S1) { int i = idx - P_W1;  g_Wr[W_P1S + 65536 + i] = to_tf32(stopW1[i]); return; }
    if (idx < P_W2) { int i = idx - P_S1;  int r = i >> 8;
                      g_Wr[W_POST2 + i] = (r < D_S) ? to_tf32(postW2[i]) : 0.f; return; }
}

__global__ void gather_emb(const int* __restrict__ tok, const float* __restrict__ emb,
                           float* __restrict__ te) {
    int r = blockIdx.x;
    int k = threadIdx.x;
    te[r * D_H + k] = to_tf32(emb[tok[r] * D_H + k]);
}

__global__ void cvec_k(const float* __restrict__ pre_b,
                       const float* __restrict__ bih, const float* __restrict__ bhh) {
    int n = blockIdx.x * 8 + (threadIdx.x >> 5);
    int lane = threadIdx.x & 31;
    float acc = 0.f;
#pragma unroll
    for (int k = lane; k < 256; k += 32)
        acc += to_tf32(pre_b[k]) * g_Wr[W_DEC + n * 256 + k];
#pragma unroll
    for (int o = 16; o; o >>= 1) acc += __shfl_down_sync(0xffffffffu, acc, o);
    if (lane == 0) g_cvec[n] = acc + bih[n] + bhh[n];
}

// ---------------- tf32 tensor-core GEMM ----------------
#define BM 128
#define BN 256
#define BK 16
#define SL 20
#define ST_AGES 3
#define AOFF(s) ((s) * (BM * SL))
#define BOFF(s) (ST_AGES * BM * SL + (s) * (BN * SL))
#define GEMM_SMEM (ST_AGES * (BM + BN) * SL * 4)

__device__ __forceinline__ void cp16(uint32_t s, const void* g) {
    asm volatile("cp.async.cg.shared.global [%0], [%1], 16;" :: "r"(s), "l"(g));
}

template<int RA>
__global__ void __launch_bounds__(256, 1) gemm_tc(
    const float* __restrict__ A, int lda, int rowlo, int rowhi, int kvalid,
    const float* __restrict__ B, int ldb,
    const float* __restrict__ bias0, const float* __restrict__ bias1,
    float* __restrict__ C, int M, int N, int K,
    int cmode, int dorelu, int doround,
    const float* __restrict__ w2, float* __restrict__ stopP)
{
    extern __shared__ float smp[];
    __shared__ float spart[4][BM];

    const int tid  = threadIdx.x;
    const int bm   = blockIdx.x * BM;
    const int bn   = blockIdx.y * BN;
    const int warp = tid >> 5, lane = tid & 31;
    const int wm   = (warp & 1) * 64;
    const int wn   = (warp >> 1) * 64;
    const int grp  = lane >> 2;
    const int tig  = lane & 3;

    float acc[4][8][4];
#pragma unroll
    for (int i = 0; i < 4; i++)
#pragma unroll
        for (int j = 0; j < 8; j++)
#pragma unroll
            for (int e = 0; e < 4; e++) acc[i][j][e] = 0.f;

    const int T = K / BK;

#define LOAD_TILE(t)                                                            \
    {                                                                           \
        int k0 = (t) * BK;                                                      \
        int sb = (t) % ST_AGES;                                                 \
        _Pragma("unroll")                                                       \
        for (int i = 0; i < 2; i++) {                                           \
            int f = i * 256 + tid, row = f >> 2, seg = (f & 3) * 4;             \
            int ar = bm + row, kk = k0 + seg;                                   \
            float* da = smp + AOFF(sb) + row * SL + seg;                        \
            if (ar >= rowlo && ar < rowhi && kk < kvalid)                       \
                cp16((uint32_t)__cvta_generic_to_shared(da),                    \
                     A + (size_t)ar * lda + kk);                                \
            else                                                                \
                *(float4*)da = make_float4(0.f, 0.f, 0.f, 0.f);                 \
        }                                                                       \
        _Pragma("unroll")                                                       \
        for (int i = 0; i < 4; i++) {                                           \
            int f = i * 256 + tid, row = f >> 2, seg = (f & 3) * 4;             \
            float* db = smp + BOFF(sb) + row * SL + seg;                        \
            cp16((uint32_t)__cvta_generic_to_shared(db),                        \
                 B + (size_t)(bn + row) * ldb + k0 + seg);                      \
        }                                                                       \
        asm volatile("cp.async.commit_group;" ::: "memory");                    \
    }

    LOAD_TILE(0);
    LOAD_TILE(1);

    for (int t = 0; t < T; t++) {
        asm volatile("cp.async.wait_group 1;" ::: "memory");
        __syncthreads();
        if (t + 2 < T) LOAD_TILE(t + 2);

        const uint32_t* as = reinterpret_cast<const uint32_t*>(smp + AOFF(t % ST_AGES));
        const uint32_t* bs = reinterpret_cast<const uint32_t*>(smp + BOFF(t % ST_AGES));

#pragma unroll
        for (int kk = 0; kk < BK; kk += 8) {
            uint32_t a[4][4], b[8][2];
            const int c0 = kk + tig;
#pragma unroll
            for (int mt = 0; mt < 4; mt++) {
                int r0 = wm + mt * 16 + grp;
                a[mt][0] = as[r0 * SL + c0];
                a[mt][1] = as[(r0 + 8) * SL + c0];
                a[mt][2] = as[r0 * SL + c0 + 4];
                a[mt][3] = as[(r0 + 8) * SL + c0 + 4];
                if (RA) {
#pragma unroll
                    for (int q = 0; q < 4; q++)
                        a[mt][q] = __float_as_uint(to_tf32(__uint_as_float(a[mt][q])));
                }
            }
#pragma unroll
            for (int nt = 0; nt < 8; nt++) {
                int n0 = wn + nt * 8 + grp;
                b[nt][0] = bs[n0 * SL + c0];
                b[nt][1] = bs[n0 * SL + c0 + 4];
            }
#pragma unroll
            for (int mt = 0; mt < 4; mt++)
#pragma unroll
                for (int nt = 0; nt < 8; nt++) {
                    asm volatile(
                        "mma.sync.aligned.m16n8k8.row.col.f32.tf32.tf32.f32 "
                        "{%0,%1,%2,%3}, {%4,%5,%6,%7}, {%8,%9}, {%0,%1,%2,%3};"
                        : "+f"(acc[mt][nt][0]), "+f"(acc[mt][nt][1]),
                          "+f"(acc[mt][nt][2]), "+f"(acc[mt][nt][3])
                        : "r"(a[mt][0]), "r"(a[mt][1]), "r"(a[mt][2]), "r"(a[mt][3]),
                          "r"(b[nt][0]), "r"(b[nt][1]));
                }
        }
        __syncthreads();
    }
#undef LOAD_TILE

    if (cmode == 2 && bn == 256) {
        float myp[4][2];
#pragma unroll
        for (int mt = 0; mt < 4; mt++) { myp[mt][0] = 0.f; myp[mt][1] = 0.f; }
#pragma unroll
        for (int nt = 0; nt < 8; nt++)
#pragma unroll
            for (int e = 0; e < 4; e++) {
                int col = bn + wn + nt * 8 + tig * 2 + (e & 1);
                float wv = __ldg(w2 + (col - 256));
                float bv = __ldg(bias0 + col);
#pragma unroll
                for (int mt = 0; mt < 4; mt++) {
                    float v = fmaxf(acc[mt][nt][e] + bv, 0.f);
                    myp[mt][e >> 1] += v * wv;
                }
            }
#pragma unroll
        for (int mt = 0; mt < 4; mt++)
#pragma unroll
            for (int h = 0; h < 2; h++) {
                float v = myp[mt][h];
                v += __shfl_xor_sync(0xffffffffu, v, 1);
                v += __shfl_xor_sync(0xffffffffu, v, 2);
                myp[mt][h] = v;
            }
        if (tig == 0) {
            int wi = warp >> 1;
#pragma unroll
            for (int mt = 0; mt < 4; mt++)
#pragma unroll
                for (int h = 0; h < 2; h++)
                    spart[wi][wm + mt * 16 + grp + 8 * h] = myp[mt][h];
        }
        __syncthreads();
        if (tid < BM)
            stopP[bm + tid] = spart[0][tid] + spart[1][tid] + spart[2][tid] + spart[3][tid];
        return;
    }

#pragma unroll
    for (int nt = 0; nt < 8; nt++) {
#pragma unroll
        for (int e = 0; e < 4; e++) {
            int col = bn + wn + nt * 8 + tig * 2 + (e & 1);
            if (col >= N) continue;
            float bv = 0.f;
            if (bias0) bv += __ldg(bias0 + col);
            if (bias1) bv += __ldg(bias1 + col);
#pragma unroll
            for (int mt = 0; mt < 4; mt++) {
                int row = bm + wm + mt * 16 + grp + ((e >> 1) << 3);
                float v = acc[mt][nt][e] + bv;
                if (dorelu) v = fmaxf(v, 0.f);
                if (doround) v = to_tf32(v);
                if (cmode == 0)
                    C[(size_t)row * N + col] = v;
                else if (cmode == 1)
                    C[(size_t)(row >> 6) * (64 * (size_t)N) + (size_t)col * 64 + (row & 63)] = v;
                else
                    C[(size_t)row * 256 + col] = v;
            }
        }
    }
}

// ---------------- stop finalize ----------------
__global__ void stopfin_k(const float* __restrict__ b2, float* __restrict__ out) {
    int r = blockIdx.x * 256 + threadIdx.x;
    if (r < M_DEC) out[r] = g_StopP[r] + b2[0];
}

// ---------------- recurrent LSTM kernels (R7, best measured) ----------------
__device__ __forceinline__ float sigmoidf_(float x) { return 1.f / (1.f + __expf(-x)); }

__device__ __forceinline__ void bar_wait(int tid, unsigned int tgt) {
    if (tid == 0) {
        unsigned int v;
        do { asm volatile("ld.acquire.gpu.u32 %0, [%1];" : "=r"(v) : "l"(&g_bar)); }
        while (v < tgt);
    }
    __syncthreads();
}
__device__ __forceinline__ void bar_arrive(int tid) {
    __syncthreads();
    if (tid == 0)
        asm volatile("red.release.gpu.add.u32 [%0], %1;" :: "l"(&g_bar), "r"(1u) : "memory");
}

#define SEQ_NB 128
#define SEQ_NT 256

// encoder: steps 0..LT
__global__ void __launch_bounds__(SEQ_NT, 2) lstm_enc_k(
    const float* __restrict__ encWhh, const int* __restrict__ tlen)
{
    __shared__ __align__(16) float Wse[8][257];
    __shared__ __align__(16) float part[8][8][64];

    const int tid = threadIdx.x;
    const int j0 = blockIdx.x * 2;

    for (int idx = tid; idx < 8 * 256; idx += SEQ_NT) {
        int gl = idx >> 8, k = idx & 255;
        int g = gl >> 1, l = gl & 1;
        Wse[gl][k] = encWhh[(g * 256 + j0 + l) * 256 + k];
    }
    const int warp = tid >> 5, lane = tid & 31;
    const int b0  = (lane & 15) * 4;
    const int gl0 = (lane >> 4) * 4;
    const int kbeg = warp * 32;
    const int ub = tid & 63, ul = tid >> 6;
    const int uj = j0 + ul;
    const bool upd = (tid < 128);
    float c_reg = 0.f;
    const int mylen = upd ? tlen[ub] : 0;
    __syncthreads();

    for (int s = 0; s < LT; s++) {
        bar_wait(tid, (unsigned int)(SEQ_NB * s));

        const int cur = s & 1, nxt = cur ^ 1;
        const float* hb = g_hbuf + cur * (D_H * NB_);

        float gvx[4];
        if (upd) {
#pragma unroll
            for (int g = 0; g < 4; g++)
                gvx[g] = __ldcg(g_XencG + (size_t)s * (G4 * NB_) + ((g * 256 + uj) << 6) + ub);
        }

        float acc[4][4];
#pragma unroll
        for (int i = 0; i < 4; i++)
#pragma unroll
            for (int g = 0; g < 4; g++) acc[i][g] = 0.f;
#pragma unroll 8
        for (int k = kbeg; k < kbeg + 32; k++) {
            float4 h4 = __ldcg((const float4*)(hb + k * 64 + b0));
            float w0 = Wse[gl0 + 0][k], w1 = Wse[gl0 + 1][k];
            float w2 = Wse[gl0 + 2][k], w3 = Wse[gl0 + 3][k];
            acc[0][0] += h4.x * w0; acc[1][0] += h4.y * w0; acc[2][0] += h4.z * w0; acc[3][0] += h4.w * w0;
            acc[0][1] += h4.x * w1; acc[1][1] += h4.y * w1; acc[2][1] += h4.z * w1; acc[3][1] += h4.w * w1;
            acc[0][2] += h4.x * w2; acc[1][2] += h4.y * w2; acc[2][2] += h4.z * w2; acc[3][2] += h4.w * w2;
            acc[0][3] += h4.x * w3; acc[1][3] += h4.y * w3; acc[2][3] += h4.z * w3; acc[3][3] += h4.w * w3;
        }
#pragma unroll
        for (int g = 0; g < 4; g++)
            *(float4*)&part[warp][gl0 + g][b0] =
                make_float4(acc[0][g], acc[1][g], acc[2][g], acc[3][g]);
        __syncthreads();

        if (upd) {
            float gv[4];
#pragma unroll
            for (int g = 0; g < 4; g++) {
                int gl = g * 2 + ul;
                float v = gvx[g];
#pragma unroll
                for (int w = 0; w < 8; w++) v += part[w][gl][ub];
                gv[g] = v;
            }
            float iv = sigmoidf_(gv[0]);
            float fv = sigmoidf_(gv[1]);
            float gg = tanhf(gv[2]);
            float ov = sigmoidf_(gv[3]);
            float c2 = fv * c_reg + iv * gg;
            float h2 = ov * tanhf(c2);
            bool m = (s < mylen);
            float hold = __ldcg(hb + uj * 64 + ub);
            c_reg = m ? c2 : c_reg;
            float hnew = m ? h2 : hold;
            g_hbuf[nxt * (D_H * NB_) + uj * 64 + ub] = hnew;
        }
        bar_arrive(tid);
    }
}

// decoder segment: steps [s0, s1e)
__global__ void __launch_bounds__(SEQ_NT, 2) lstm_dec_k(
    const float* __restrict__ decWhh, int s0, int s1e)
{
    __shared__ __align__(16) float2 Wsd2[8][256];
    __shared__ __align__(16) float part[8][8][64];

    const int tid = threadIdx.x;
    const int j0 = blockIdx.x * 2;

    for (int idx = tid; idx < 8 * 256; idx += SEQ_NT) {
        int gl = idx >> 8, k = idx & 255;
        int g = gl >> 1, l = gl & 1;
        float wd = decWhh[(g * 256 + j0 + l) * 256 + k];
        Wsd2[gl][k] = make_float2(wd, wd);
    }
    const int warp = tid >> 5, lane = tid & 31;
    const int b0  = (lane & 15) * 4;
    const int gl0 = (lane >> 4) * 4;
    const int kbeg = warp * 32;
    const int ub = tid & 63, ul = tid >> 6;
    const int uj = j0 + ul;
    const bool upd = (tid < 128);
    float c_reg = 0.f;
    if (upd && s0 > LT) c_reg = g_cbuf[uj * 64 + ub];
    __syncthreads();

    for (int s = s0; s < s1e; s++) {
        bar_wait(tid, (unsigned int)(SEQ_NB * s));

        const int cur = s & 1, nxt = cur ^ 1;
        const float* hb = g_hbuf + cur * (D_H * NB_);
        const int t = s - LT;

        float gvx[4];
        if (upd) {
            if (t < 800) {
#pragma unroll
                for (int g = 0; g < 4; g++)
                    gvx[g] = __ldcg(g_XdG + (size_t)t * ((size_t)G4 * NB_)
                                    + ((g * 256 + uj) << 6) + ub);
            } else {
#pragma unroll
                for (int g = 0; g < 4; g++)
                    gvx[g] = __ldg(g_cvec + g * 256 + uj);
            }
        }

        unsigned long long accp[2][4];
#pragma unroll
        for (int p = 0; p < 2; p++)
#pragma unroll
            for (int g = 0; g < 4; g++) accp[p][g] = 0ull;
#pragma unroll 8
        for (int k = kbeg; k < kbeg + 32; k++) {
            ulonglong2 hq = __ldcg((const ulonglong2*)(hb + k * 64 + b0));
            unsigned long long w0 = *(const unsigned long long*)&Wsd2[gl0 + 0][k];
            unsigned long long w1 = *(const unsigned long long*)&Wsd2[gl0 + 1][k];
            unsigned long long w2 = *(const unsigned long long*)&Wsd2[gl0 + 2][k];
            unsigned long long w3 = *(const unsigned long long*)&Wsd2[gl0 + 3][k];
            asm("fma.rn.f32x2 %0, %1, %2, %0;" : "+l"(accp[0][0]) : "l"(hq.x), "l"(w0));
            asm("fma.rn.f32x2 %0, %1, %2, %0;" : "+l"(accp[1][0]) : "l"(hq.y), "l"(w0));
            asm("fma.rn.f32x2 %0, %1, %2, %0;" : "+l"(accp[0][1]) : "l"(hq.x), "l"(w1));
            asm("fma.rn.f32x2 %0, %1, %2, %0;" : "+l"(accp[1][1]) : "l"(hq.y), "l"(w1));
            asm("fma.rn.f32x2 %0, %1, %2, %0;" : "+l"(accp[0][2]) : "l"(hq.x), "l"(w2));
            asm("fma.rn.f32x2 %0, %1, %2, %0;" : "+l"(accp[1][2]) : "l"(hq.y), "l"(w2));
            asm("fma.rn.f32x2 %0, %1, %2, %0;" : "+l"(accp[0][3]) : "l"(hq.x), "l"(w3));
            asm("fma.rn.f32x2 %0, %1, %2, %0;" : "+l"(accp[1][3]) : "l"(hq.y), "l"(w3));
        }
#pragma unroll
        for (int g = 0; g < 4; g++) {
            float2 f0 = *(float2*)&accp[0][g];
            float2 f1 = *(float2*)&accp[1][g];
            *(float4*)&part[warp][gl0 + g][b0] = make_float4(f0.x, f0.y, f1.x, f1.y);
        }
        __syncthreads();

        if (upd) {
            float gv[4];
#pragma unroll
            for (int g = 0; g < 4; g++) {
                int gl = g * 2 + ul;
                float v = gvx[g];
#pragma unroll
                for (int w = 0; w < 8; w++) v += part[w][gl][ub];
                gv[g] = v;
            }
            if (s == LT)
                c_reg = __ldcg(hb + uj * 64 + ub);

            float iv = sigmoidf_(gv[0]);
            float fv = sigmoidf_(gv[1]);
            float gg = tanhf(gv[2]);
            float ov = sigmoidf_(gv[3]);
            float c2 = fv * c_reg + iv * gg;
            float h2 = ov * tanhf(c2);
            c_reg = c2;
            g_H[(size_t)t * (NB_ * D_H) + ub * D_H + uj] = to_tf32(h2);
            g_hbuf[nxt * (D_H * NB_) + uj * 64 + ub] = h2;
        }
        bar_arrive(tid);
    }
    if (upd) g_cbuf[uj * 64 + ub] = c_reg;
}

// ---------------- launch ----------------
extern "C" void kernel_launch(void* const* d_in, const int* in_sizes, int n_in,
                              void* d_out, int out_size) {
    const int*   token_pad     = (const int*)  d_in[0];
    const int*   token_lengths = (const int*)  d_in[1];
    const float* S_true        = (const float*)d_in[2];
    const float* emb           = (const float*)d_in[3];
    const float* enc_Wih       = (const float*)d_in[4];
    const float* enc_Whh       = (const float*)d_in[5];
    const float* enc_bih       = (const float*)d_in[6];
    const float* enc_bhh       = (const float*)d_in[7];
    const float* dec_Wih       = (const float*)d_in[8];
    const float* dec_Whh       = (const float*)d_in[9];
    const float* dec_bih       = (const float*)d_in[10];
    const float* dec_bhh       = (const float*)d_in[11];
    const float* pre_W         = (const float*)d_in[12];
    const float* pre_b         = (const float*)d_in[13];
    const float* post_W1       = (const float*)d_in[14];
    const float* post_b1       = (const float*)d_in[15];
    const float* post_W2       = (const float*)d_in[16];
    const float* post_b2       = (const float*)d_in[17];
    const float* stop_W1       = (const float*)d_in[18];
    const float* stop_b1       = (const float*)d_in[19];
    const float* stop_W2       = (const float*)d_in[20];
    const float* stop_b2       = (const float*)d_in[21];
    float* out = (float*)d_out;

    float *pTE, *pXencG, *pXd, *pXdG, *pH, *pHid, *pWr, *pStopP, *pBcat;
    cudaGetSymbolAddress((void**)&pTE,    g_TE);
    cudaGetSymbolAddress((void**)&pXencG, g_XencG);
    cudaGetSymbolAddress((void**)&pXd,    g_Xd);
    cudaGetSymbolAddress((void**)&pXdG,   g_XdG);
    cudaGetSymbolAddress((void**)&pH,     g_H);
    cudaGetSymbolAddress((void**)&pHid,   g_Hid);
    cudaGetSymbolAddress((void**)&pWr,    g_Wr);
    cudaGetSymbolAddress((void**)&pStopP, g_StopP);
    cudaGetSymbolAddress((void**)&pBcat,  g_bcat);

    static bool s_init = false;
    static cudaStream_t s1, s2;
    static cudaEvent_t evR, evJ, evL[NSEG], evDs[NSEG];
    if (!s_init) {
        s_init = true;
        cudaStreamCreateWithFlags(&s1, cudaStreamNonBlocking);
        cudaStreamCreateWithFlags(&s2, cudaStreamNonBlocking);
        cudaEventCreateWithFlags(&evR, cudaEventDisableTiming);
        cudaEventCreateWithFlags(&evJ, cudaEventDisableTiming);
        for (int i = 0; i < NSEG; i++) {
            cudaEventCreateWithFlags(&evL[i],  cudaEventDisableTiming);
            cudaEventCreateWithFlags(&evDs[i], cudaEventDisableTiming);
        }
        cudaFuncSetAttribute(gemm_tc<0>, cudaFuncAttributeMaxDynamicSharedMemorySize, GEMM_SMEM);
        cudaFuncSetAttribute(gemm_tc<1>, cudaFuncAttributeMaxDynamicSharedMemorySize, GEMM_SMEM);
    }

    // ---- stream 0: prep + encoder ----
    prep_k<<<(P_W2 + 255) / 256, 256>>>(enc_Wih, dec_Wih, pre_W, post_W1, stop_W1, post_W2,
                                        post_b1, stop_b1);
    gather_emb<<<M_ENC, 256>>>(token_pad, emb, pTE);
    cudaEventRecord(evR, 0);
    gemm_tc<0><<<dim3(M_ENC/128, G4/256), 256, GEMM_SMEM>>>(pTE, 256, 0, M_ENC, 256,
        pWr + W_ENC, 256, enc_bih, enc_bhh, pXencG, M_ENC, G4, 256, 1, 0, 0, nullptr, nullptr);
    lstm_enc_k<<<SEQ_NB, SEQ_NT>>>(enc_Whh, token_lengths);

    // ---- s1: cvec + 4 pipelined (pre-net, dec-gate) chunks, overlapping the encoder ----
    cudaStreamWaitEvent(s1, evR, 0);
    cvec_k<<<G4/8, 256, 0, s1>>>(pre_b, dec_bih, dec_bhh);
    {
        const int rs[NSEG + 1] = {0, 16000, 32000, 48000, M_VAL};
        for (int i = 0; i < NSEG; i++) {
            int r0 = rs[i], Mseg = rs[i + 1] - rs[i];
            gemm_tc<1><<<dim3(Mseg/128, 1), 256, GEMM_SMEM, s1>>>(
                S_true + (size_t)r0 * D_S, D_S, (i == 0 ? 64 : 0), Mseg, D_S,
                pWr + W_PRE, KP_S, pre_b, nullptr, pXd + (size_t)r0 * D_H,
                Mseg, D_H, KP_S, 0, 0, 1, nullptr, nullptr);
            gemm_tc<0><<<dim3(Mseg/128, G4/256), 256, GEMM_SMEM, s1>>>(
                pXd + (size_t)r0 * D_H, 256, 0, Mseg, 256,
                pWr + W_DEC, 256, dec_bih, dec_bhh, pXdG + (size_t)r0 * G4,
                Mseg, G4, 256, 1, 0, 0, nullptr, nullptr);
            cudaEventRecord(evDs[i], s1);
        }
    }

    // ---- stream 0: decoder recurrence, each segment gated on its own gate chunk ----
    for (int i = 0; i < NSEG; i++) {
        cudaStreamWaitEvent(0, evDs[i], 0);
        lstm_dec_k<<<SEQ_NB, SEQ_NT>>>(dec_Whh, LT + i * SEG_STEPS, LT + (i + 1) * SEG_STEPS);
        cudaEventRecord(evL[i], 0);
    }

    // ---- s2: per-segment post-net chunks overlap the decoder recurrence ----
    for (int i = 0; i < NSEG; i++) {
        cudaStreamWaitEvent(s2, evL[i], 0);
        const float* Hc  = pH   + (size_t)SEG_ROWS * i * 256;
        float*       Hic = pHid + (size_t)SEG_ROWS * i * 256;
        gemm_tc<0><<<dim3(SEG_ROWS/128, 2), 256, GEMM_SMEM, s2>>>(Hc, 256, 0, SEG_ROWS, 256,
            pWr + W_P1S, 256, pBcat, nullptr, Hic, SEG_ROWS, 512, 256, 2, 1, 1,
            stop_W2, pStopP + (size_t)SEG_ROWS * i);
        gemm_tc<0><<<dim3(SEG_ROWS/128, 3), 256, GEMM_SMEM, s2>>>(Hic, 256, 0, SEG_ROWS, 256,
            pWr + W_POST2, 256, post_b2, nullptr, out + (size_t)SEG_ROWS * i * D_S,
            SEG_ROWS, D_S, 256, 0, 0, 0, nullptr, nullptr);
    }
    stopfin_k<<<(M_DEC+255)/256, 256, 0, s2>>>(stop_b2, out + STOP_OFF);
    cudaEventRecord(evJ, s2);

    cudaStreamWaitEvent(0, evJ, 0);
}

// round 15
// speedup vs baseline: 1.2474x; 1.0366x over previous
#include <cuda_runtime.h>
#include <cuda_bf16.h>
#include <math.h>
#include <stdint.h>

// ---------------- problem constants ----------------
#define D_H 256
#define D_S 552
#define LT  128
#define NB_ 64
#define MAXDEC 1000
#define G4 1024
#define M_ENC (LT*NB_)       // 8192
#define M_DEC (MAXDEC*NB_)   // 64000
#define M_VAL 51200          // rows with non-trivial S_in
#define STOP_OFF ((size_t)M_DEC * D_S)
#define KP_S 560
#define NSEGD 10             // decoder segments
#define SEG_STEPS 100
#define SEG_ROWS  (SEG_STEPS*NB_)   // 6400

// ---------------- device scratch ----------------
__device__ __align__(256) float g_TE[M_ENC * D_H];
__device__ __align__(256) float g_XencG[M_ENC * G4];
__device__ __align__(256) float g_Xd[(size_t)M_VAL * D_H];
__device__ __align__(256) float g_XdG[(size_t)M_VAL * G4];
__device__ __align__(256) float g_H[(size_t)M_DEC * D_H];
__device__ __align__(256) float g_Hid[(size_t)M_DEC * D_H];
__device__ __align__(256) float g_StopP[M_DEC];
__device__ __align__(256) float g_Wr[995328];
__device__ __align__(256) float g_bcat[512];
__device__ __align__(256) float g_cvec[G4];
__device__ float g_hbuf[2 * D_H * NB_];
__device__ float g_cbuf[D_H * NB_];
__device__ unsigned int g_bar;

#define W_ENC   0
#define W_DEC   262144
#define W_PRE   524288
#define W_P1S   667648
#define W_POST2 798720

__device__ __forceinline__ float to_tf32(float x) {
    float r; asm("cvt.rna.tf32.f32 %0, %1;" : "=f"(r) : "f"(x)); return r;
}

// ---------------- fused prep ----------------
#define P_HB  32768
#define P_BC  (P_HB + 512)
#define P_ENC (P_BC + 262144)
#define P_DEC (P_ENC + 262144)
#define P_PRE (P_DEC + 143360)
#define P_W1  (P_PRE + 65536)
#define P_S1  (P_W1 + 65536)
#define P_W2  (P_S1 + 196608)

__global__ void prep_k(const float* __restrict__ encWih, const float* __restrict__ decWih,
                       const float* __restrict__ preW,  const float* __restrict__ postW1,
                       const float* __restrict__ stopW1,const float* __restrict__ postW2,
                       const float* __restrict__ b1,    const float* __restrict__ b2) {
    int idx = blockIdx.x * 256 + threadIdx.x;
    if (idx == 0) g_bar = 0u;
    if (idx < P_HB) { g_hbuf[idx] = 0.f; return; }
    if (idx < P_BC) { int i = idx - P_HB; g_bcat[i] = (i < 256) ? b1[i] : b2[i - 256]; return; }
    if (idx < P_ENC){ int i = idx - P_BC; g_Wr[W_ENC + i] = to_tf32(encWih[i]); return; }
    if (idx < P_DEC){ int i = idx - P_ENC; g_Wr[W_DEC + i] = to_tf32(decWih[i]); return; }
    if (idx < P_PRE){ int i = idx - P_DEC; int r = i / KP_S, c = i - r * KP_S;
                      g_Wr[W_PRE + i] = (c < D_S) ? to_tf32(preW[r * D_S + c]) : 0.f; return; }
    if (idx < P_W1) { int i = idx - P_PRE; g_Wr[W_P1S + i] = to_tf32(postW1[i]); return; }
    if (idx < P_S1) { int i = idx - P_W1;  g_Wr[W_P1S + 65536 + i] = to_tf32(stopW1[i]); return; }
    if (idx < P_W2) { int i = idx - P_S1;  int r = i >> 8;
                      g_Wr[W_POST2 + i] = (r < D_S) ? to_tf32(postW2[i]) : 0.f; return; }
}

__global__ void gather_emb(const int* __restrict__ tok, const float* __restrict__ emb,
                           float* __restrict__ te) {
    int r = blockIdx.x;
    int k = threadIdx.x;
    te[r * D_H + k] = to_tf32(emb[tok[r] * D_H + k]);
}

__global__ void cvec_k(const float* __restrict__ pre_b,
                       const float* __restrict__ bih, const float* __restrict__ bhh) {
    int n = blockIdx.x * 8 + (threadIdx.x >> 5);
    int lane = threadIdx.x & 31;
    float acc = 0.f;
#pragma unroll
    for (int k = lane; k < 256; k += 32)
        acc += to_tf32(pre_b[k]) * g_Wr[W_DEC + n * 256 + k];
#pragma unroll
    for (int o = 16; o; o >>= 1) acc += __shfl_down_sync(0xffffffffu, acc, o);
    if (lane == 0) g_cvec[n] = acc + bih[n] + bhh[n];
}

// ---------------- tf32 tensor-core GEMM ----------------
#define BM 128
#define BN 256
#define BK 16
#define SL 20
#define ST_AGES 3
#define AOFF(s) ((s) * (BM * SL))
#define BOFF(s) (ST_AGES * BM * SL + (s) * (BN * SL))
#define GEMM_SMEM (ST_AGES * (BM + BN) * SL * 4)

__device__ __forceinline__ void cp16(uint32_t s, const void* g) {
    asm volatile("cp.async.cg.shared.global [%0], [%1], 16;" :: "r"(s), "l"(g));
}

template<int RA>
__global__ void __launch_bounds__(256, 1) gemm_tc(
    const float* __restrict__ A, int lda, int rowlo, int rowhi, int kvalid,
    const float* __restrict__ B, int ldb,
    const float* __restrict__ bias0, const float* __restrict__ bias1,
    float* __restrict__ C, int M, int N, int K,
    int cmode, int dorelu, int doround,
    const float* __restrict__ w2, float* __restrict__ stopP)
{
    extern __shared__ float smp[];
    __shared__ float spart[4][BM];

    const int tid  = threadIdx.x;
    const int bm   = blockIdx.x * BM;
    const int bn   = blockIdx.y * BN;
    const int warp = tid >> 5, lane = tid & 31;
    const int wm   = (warp & 1) * 64;
    const int wn   = (warp >> 1) * 64;
    const int grp  = lane >> 2;
    const int tig  = lane & 3;

    float acc[4][8][4];
#pragma unroll
    for (int i = 0; i < 4; i++)
#pragma unroll
        for (int j = 0; j < 8; j++)
#pragma unroll
            for (int e = 0; e < 4; e++) acc[i][j][e] = 0.f;

    const int T = K / BK;

#define LOAD_TILE(t)                                                            \
    {                                                                           \
        int k0 = (t) * BK;                                                      \
        int sb = (t) % ST_AGES;                                                 \
        _Pragma("unroll")                                                       \
        for (int i = 0; i < 2; i++) {                                           \
            int f = i * 256 + tid, row = f >> 2, seg = (f & 3) * 4;             \
            int ar = bm + row, kk = k0 + seg;                                   \
            float* da = smp + AOFF(sb) + row * SL + seg;                        \
            if (ar >= rowlo && ar < rowhi && kk < kvalid)                       \
                cp16((uint32_t)__cvta_generic_to_shared(da),                    \
                     A + (size_t)ar * lda + kk);                                \
            else                                                                \
                *(float4*)da = make_float4(0.f, 0.f, 0.f, 0.f);                 \
        }                                                                       \
        _Pragma("unroll")                                                       \
        for (int i = 0; i < 4; i++) {                                           \
            int f = i * 256 + tid, row = f >> 2, seg = (f & 3) * 4;             \
            float* db = smp + BOFF(sb) + row * SL + seg;                        \
            cp16((uint32_t)__cvta_generic_to_shared(db),                        \
                 B + (size_t)(bn + row) * ldb + k0 + seg);                      \
        }                                                                       \
        asm volatile("cp.async.commit_group;" ::: "memory");                    \
    }

    LOAD_TILE(0);
    LOAD_TILE(1);

    for (int t = 0; t < T; t++) {
        asm volatile("cp.async.wait_group 1;" ::: "memory");
        __syncthreads();
        if (t + 2 < T) LOAD_TILE(t + 2);

        const uint32_t* as = reinterpret_cast<const uint32_t*>(smp + AOFF(t % ST_AGES));
        const uint32_t* bs = reinterpret_cast<const uint32_t*>(smp + BOFF(t % ST_AGES));

#pragma unroll
        for (int kk = 0; kk < BK; kk += 8) {
            uint32_t a[4][4], b[8][2];
            const int c0 = kk + tig;
#pragma unroll
            for (int mt = 0; mt < 4; mt++) {
                int r0 = wm + mt * 16 + grp;
                a[mt][0] = as[r0 * SL + c0];
                a[mt][1] = as[(r0 + 8) * SL + c0];
                a[mt][2] = as[r0 * SL + c0 + 4];
                a[mt][3] = as[(r0 + 8) * SL + c0 + 4];
                if (RA) {
#pragma unroll
                    for (int q = 0; q < 4; q++)
                        a[mt][q] = __float_as_uint(to_tf32(__uint_as_float(a[mt][q])));
                }
            }
#pragma unroll
            for (int nt = 0; nt < 8; nt++) {
                int n0 = wn + nt * 8 + grp;
                b[nt][0] = bs[n0 * SL + c0];
                b[nt][1] = bs[n0 * SL + c0 + 4];
            }
#pragma unroll
            for (int mt = 0; mt < 4; mt++)
#pragma unroll
                for (int nt = 0; nt < 8; nt++) {
                    asm volatile(
                        "mma.sync.aligned.m16n8k8.row.col.f32.tf32.tf32.f32 "
                        "{%0,%1,%2,%3}, {%4,%5,%6,%7}, {%8,%9}, {%0,%1,%2,%3};"
                        : "+f"(acc[mt][nt][0]), "+f"(acc[mt][nt][1]),
                          "+f"(acc[mt][nt][2]), "+f"(acc[mt][nt][3])
                        : "r"(a[mt][0]), "r"(a[mt][1]), "r"(a[mt][2]), "r"(a[mt][3]),
                          "r"(b[nt][0]), "r"(b[nt][1]));
                }
        }
        __syncthreads();
    }
#undef LOAD_TILE

    if (cmode == 2 && bn == 256) {
        float myp[4][2];
#pragma unroll
        for (int mt = 0; mt < 4; mt++) { myp[mt][0] = 0.f; myp[mt][1] = 0.f; }
#pragma unroll
        for (int nt = 0; nt < 8; nt++)
#pragma unroll
            for (int e = 0; e < 4; e++) {
                int col = bn + wn + nt * 8 + tig * 2 + (e & 1);
                float wv = __ldg(w2 + (col - 256));
                float bv = __ldg(bias0 + col);
#pragma unroll
                for (int mt = 0; mt < 4; mt++) {
                    float v = fmaxf(acc[mt][nt][e] + bv, 0.f);
                    myp[mt][e >> 1] += v * wv;
                }
            }
#pragma unroll
        for (int mt = 0; mt < 4; mt++)
#pragma unroll
            for (int h = 0; h < 2; h++) {
                float v = myp[mt][h];
                v += __shfl_xor_sync(0xffffffffu, v, 1);
                v += __shfl_xor_sync(0xffffffffu, v, 2);
                myp[mt][h] = v;
            }
        if (tig == 0) {
            int wi = warp >> 1;
#pragma unroll
            for (int mt = 0; mt < 4; mt++)
#pragma unroll
                for (int h = 0; h < 2; h++)
                    spart[wi][wm + mt * 16 + grp + 8 * h] = myp[mt][h];
        }
        __syncthreads();
        if (tid < BM)
            stopP[bm + tid] = spart[0][tid] + spart[1][tid] + spart[2][tid] + spart[3][tid];
        return;
    }

#pragma unroll
    for (int nt = 0; nt < 8; nt++) {
#pragma unroll
        for (int e = 0; e < 4; e++) {
            int col = bn + wn + nt * 8 + tig * 2 + (e & 1);
            if (col >= N) continue;
            float bv = 0.f;
            if (bias0) bv += __ldg(bias0 + col);
            if (bias1) bv += __ldg(bias1 + col);
#pragma unroll
            for (int mt = 0; mt < 4; mt++) {
                int row = bm + wm + mt * 16 + grp + ((e >> 1) << 3);
                float v = acc[mt][nt][e] + bv;
                if (dorelu) v = fmaxf(v, 0.f);
                if (doround) v = to_tf32(v);
                if (cmode == 0)
                    C[(size_t)row * N + col] = v;
                else if (cmode == 1)
                    C[(size_t)(row >> 6) * (64 * (size_t)N) + (size_t)col * 64 + (row & 63)] = v;
                else
                    C[(size_t)row * 256 + col] = v;
            }
        }
    }
}

// ---------------- stop finalize ----------------
__global__ void stopfin_k(const float* __restrict__ b2, float* __restrict__ out) {
    int r = blockIdx.x * 256 + threadIdx.x;
    if (r < M_DEC) out[r] = g_StopP[r] + b2[0];
}

// ---------------- recurrent LSTM kernels (R7, best measured) ----------------
__device__ __forceinline__ float sigmoidf_(float x) { return 1.f / (1.f + __expf(-x)); }

__device__ __forceinline__ void bar_wait(int tid, unsigned int tgt) {
    if (tid == 0) {
        unsigned int v;
        do { asm volatile("ld.acquire.gpu.u32 %0, [%1];" : "=r"(v) : "l"(&g_bar)); }
        while (v < tgt);
    }
    __syncthreads();
}
__device__ __forceinline__ void bar_arrive(int tid) {
    __syncthreads();
    if (tid == 0)
        asm volatile("red.release.gpu.add.u32 [%0], %1;" :: "l"(&g_bar), "r"(1u) : "memory");
}

#define SEQ_NB 128
#define SEQ_NT 256

// encoder: steps 0..LT
__global__ void __launch_bounds__(SEQ_NT, 2) lstm_enc_k(
    const float* __restrict__ encWhh, const int* __restrict__ tlen)
{
    __shared__ __align__(16) float Wse[8][257];
    __shared__ __align__(16) float part[8][8][64];

    const int tid = threadIdx.x;
    const int j0 = blockIdx.x * 2;

    for (int idx = tid; idx < 8 * 256; idx += SEQ_NT) {
        int gl = idx >> 8, k = idx & 255;
        int g = gl >> 1, l = gl & 1;
        Wse[gl][k] = encWhh[(g * 256 + j0 + l) * 256 + k];
    }
    const int warp = tid >> 5, lane = tid & 31;
    const int b0  = (lane & 15) * 4;
    const int gl0 = (lane >> 4) * 4;
    const int kbeg = warp * 32;
    const int ub = tid & 63, ul = tid >> 6;
    const int uj = j0 + ul;
    const bool upd = (tid < 128);
    float c_reg = 0.f;
    const int mylen = upd ? tlen[ub] : 0;
    __syncthreads();

    for (int s = 0; s < LT; s++) {
        bar_wait(tid, (unsigned int)(SEQ_NB * s));

        const int cur = s & 1, nxt = cur ^ 1;
        const float* hb = g_hbuf + cur * (D_H * NB_);

        float gvx[4];
        if (upd) {
#pragma unroll
            for (int g = 0; g < 4; g++)
                gvx[g] = __ldcg(g_XencG + (size_t)s * (G4 * NB_) + ((g * 256 + uj) << 6) + ub);
        }

        float acc[4][4];
#pragma unroll
        for (int i = 0; i < 4; i++)
#pragma unroll
            for (int g = 0; g < 4; g++) acc[i][g] = 0.f;
#pragma unroll 8
        for (int k = kbeg; k < kbeg + 32; k++) {
            float4 h4 = __ldcg((const float4*)(hb + k * 64 + b0));
            float w0 = Wse[gl0 + 0][k], w1 = Wse[gl0 + 1][k];
            float w2 = Wse[gl0 + 2][k], w3 = Wse[gl0 + 3][k];
            acc[0][0] += h4.x * w0; acc[1][0] += h4.y * w0; acc[2][0] += h4.z * w0; acc[3][0] += h4.w * w0;
            acc[0][1] += h4.x * w1; acc[1][1] += h4.y * w1; acc[2][1] += h4.z * w1; acc[3][1] += h4.w * w1;
            acc[0][2] += h4.x * w2; acc[1][2] += h4.y * w2; acc[2][2] += h4.z * w2; acc[3][2] += h4.w * w2;
            acc[0][3] += h4.x * w3; acc[1][3] += h4.y * w3; acc[2][3] += h4.z * w3; acc[3][3] += h4.w * w3;
        }
#pragma unroll
        for (int g = 0; g < 4; g++)
            *(float4*)&part[warp][gl0 + g][b0] =
                make_float4(acc[0][g], acc[1][g], acc[2][g], acc[3][g]);
        __syncthreads();

        if (upd) {
            float gv[4];
#pragma unroll
            for (int g = 0; g < 4; g++) {
                int gl = g * 2 + ul;
                float v = gvx[g];
#pragma unroll
                for (int w = 0; w < 8; w++) v += part[w][gl][ub];
                gv[g] = v;
            }
            float iv = sigmoidf_(gv[0]);
            float fv = sigmoidf_(gv[1]);
            float gg = tanhf(gv[2]);
            float ov = sigmoidf_(gv[3]);
            float c2 = fv * c_reg + iv * gg;
            float h2 = ov * tanhf(c2);
            bool m = (s < mylen);
            float hold = __ldcg(hb + uj * 64 + ub);
            c_reg = m ? c2 : c_reg;
            float hnew = m ? h2 : hold;
            g_hbuf[nxt * (D_H * NB_) + uj * 64 + ub] = hnew;
        }
        bar_arrive(tid);
    }
}

// decoder segment: steps [s0, s1e)
__global__ void __launch_bounds__(SEQ_NT, 2) lstm_dec_k(
    const float* __restrict__ decWhh, int s0, int s1e)
{
    __shared__ __align__(16) float2 Wsd2[8][256];
    __shared__ __align__(16) float part[8][8][64];

    const int tid = threadIdx.x;
    const int j0 = blockIdx.x * 2;

    for (int idx = tid; idx < 8 * 256; idx += SEQ_NT) {
        int gl = idx >> 8, k = idx & 255;
        int g = gl >> 1, l = gl & 1;
        float wd = decWhh[(g * 256 + j0 + l) * 256 + k];
        Wsd2[gl][k] = make_float2(wd, wd);
    }
    const int warp = tid >> 5, lane = tid & 31;
    const int b0  = (lane & 15) * 4;
    const int gl0 = (lane >> 4) * 4;
    const int kbeg = warp * 32;
    const int ub = tid & 63, ul = tid >> 6;
    const int uj = j0 + ul;
    const bool upd = (tid < 128);
    float c_reg = 0.f;
    if (upd && s0 > LT) c_reg = g_cbuf[uj * 64 + ub];
    __syncthreads();

    for (int s = s0; s < s1e; s++) {
        bar_wait(tid, (unsigned int)(SEQ_NB * s));

        const int cur = s & 1, nxt = cur ^ 1;
        const float* hb = g_hbuf + cur * (D_H * NB_);
        const int t = s - LT;

        float gvx[4];
        if (upd) {
            if (t < 800) {
#pragma unroll
                for (int g = 0; g < 4; g++)
                    gvx[g] = __ldcg(g_XdG + (size_t)t * ((size_t)G4 * NB_)
                                    + ((g * 256 + uj) << 6) + ub);
            } else {
#pragma unroll
                for (int g = 0; g < 4; g++)
                    gvx[g] = __ldg(g_cvec + g * 256 + uj);
            }
        }

        unsigned long long accp[2][4];
#pragma unroll
        for (int p = 0; p < 2; p++)
#pragma unroll
            for (int g = 0; g < 4; g++) accp[p][g] = 0ull;
#pragma unroll 8
        for (int k = kbeg; k < kbeg + 32; k++) {
            ulonglong2 hq = __ldcg((const ulonglong2*)(hb + k * 64 + b0));
            unsigned long long w0 = *(const unsigned long long*)&Wsd2[gl0 + 0][k];
            unsigned long long w1 = *(const unsigned long long*)&Wsd2[gl0 + 1][k];
            unsigned long long w2 = *(const unsigned long long*)&Wsd2[gl0 + 2][k];
            unsigned long long w3 = *(const unsigned long long*)&Wsd2[gl0 + 3][k];
            asm("fma.rn.f32x2 %0, %1, %2, %0;" : "+l"(accp[0][0]) : "l"(hq.x), "l"(w0));
            asm("fma.rn.f32x2 %0, %1, %2, %0;" : "+l"(accp[1][0]) : "l"(hq.y), "l"(w0));
            asm("fma.rn.f32x2 %0, %1, %2, %0;" : "+l"(accp[0][1]) : "l"(hq.x), "l"(w1));
            asm("fma.rn.f32x2 %0, %1, %2, %0;" : "+l"(accp[1][1]) : "l"(hq.y), "l"(w1));
            asm("fma.rn.f32x2 %0, %1, %2, %0;" : "+l"(accp[0][2]) : "l"(hq.x), "l"(w2));
            asm("fma.rn.f32x2 %0, %1, %2, %0;" : "+l"(accp[1][2]) : "l"(hq.y), "l"(w2));
            asm("fma.rn.f32x2 %0, %1, %2, %0;" : "+l"(accp[0][3]) : "l"(hq.x), "l"(w3));
            asm("fma.rn.f32x2 %0, %1, %2, %0;" : "+l"(accp[1][3]) : "l"(hq.y), "l"(w3));
        }
#pragma unroll
        for (int g = 0; g < 4; g++) {
            float2 f0 = *(float2*)&accp[0][g];
            float2 f1 = *(float2*)&accp[1][g];
            *(float4*)&part[warp][gl0 + g][b0] = make_float4(f0.x, f0.y, f1.x, f1.y);
        }
        __syncthreads();

        if (upd) {
            float gv[4];
#pragma unroll
            for (int g = 0; g < 4; g++) {
                int gl = g * 2 + ul;
                float v = gvx[g];
#pragma unroll
                for (int w = 0; w < 8; w++) v += part[w][gl][ub];
                gv[g] = v;
            }
            if (s == LT)
                c_reg = __ldcg(hb + uj * 64 + ub);

            float iv = sigmoidf_(gv[0]);
            float fv = sigmoidf_(gv[1]);
            float gg = tanhf(gv[2]);
            float ov = sigmoidf_(gv[3]);
            float c2 = fv * c_reg + iv * gg;
            float h2 = ov * tanhf(c2);
            c_reg = c2;
            g_H[(size_t)t * (NB_ * D_H) + ub * D_H + uj] = to_tf32(h2);
            g_hbuf[nxt * (D_H * NB_) + uj * 64 + ub] = h2;
        }
        bar_arrive(tid);
    }
    if (upd) g_cbuf[uj * 64 + ub] = c_reg;
}

// ---------------- launch ----------------
extern "C" void kernel_launch(void* const* d_in, const int* in_sizes, int n_in,
                              void* d_out, int out_size) {
    const int*   token_pad     = (const int*)  d_in[0];
    const int*   token_lengths = (const int*)  d_in[1];
    const float* S_true        = (const float*)d_in[2];
    const float* emb           = (const float*)d_in[3];
    const float* enc_Wih       = (const float*)d_in[4];
    const float* enc_Whh       = (const float*)d_in[5];
    const float* enc_bih       = (const float*)d_in[6];
    const float* enc_bhh       = (const float*)d_in[7];
    const float* dec_Wih       = (const float*)d_in[8];
    const float* dec_Whh       = (const float*)d_in[9];
    const float* dec_bih       = (const float*)d_in[10];
    const float* dec_bhh       = (const float*)d_in[11];
    const float* pre_W         = (const float*)d_in[12];
    const float* pre_b         = (const float*)d_in[13];
    const float* post_W1       = (const float*)d_in[14];
    const float* post_b1       = (const float*)d_in[15];
    const float* post_W2       = (const float*)d_in[16];
    const float* post_b2       = (const float*)d_in[17];
    const float* stop_W1       = (const float*)d_in[18];
    const float* stop_b1       = (const float*)d_in[19];
    const float* stop_W2       = (const float*)d_in[20];
    const float* stop_b2       = (const float*)d_in[21];
    float* out = (float*)d_out;

    float *pTE, *pXencG, *pXd, *pXdG, *pH, *pHid, *pWr, *pStopP, *pBcat;
    cudaGetSymbolAddress((void**)&pTE,    g_TE);
    cudaGetSymbolAddress((void**)&pXencG, g_XencG);
    cudaGetSymbolAddress((void**)&pXd,    g_Xd);
    cudaGetSymbolAddress((void**)&pXdG,   g_XdG);
    cudaGetSymbolAddress((void**)&pH,     g_H);
    cudaGetSymbolAddress((void**)&pHid,   g_Hid);
    cudaGetSymbolAddress((void**)&pWr,    g_Wr);
    cudaGetSymbolAddress((void**)&pStopP, g_StopP);
    cudaGetSymbolAddress((void**)&pBcat,  g_bcat);

    static bool s_init = false;
    static cudaStream_t s1, s1b, s2;
    static cudaEvent_t evR, evD, evJ, evPA, evPB, evL[NSEGD];
    if (!s_init) {
        s_init = true;
        cudaStreamCreateWithFlags(&s1,  cudaStreamNonBlocking);
        cudaStreamCreateWithFlags(&s1b, cudaStreamNonBlocking);
        cudaStreamCreateWithFlags(&s2,  cudaStreamNonBlocking);
        cudaEventCreateWithFlags(&evR,  cudaEventDisableTiming);
        cudaEventCreateWithFlags(&evD,  cudaEventDisableTiming);
        cudaEventCreateWithFlags(&evJ,  cudaEventDisableTiming);
        cudaEventCreateWithFlags(&evPA, cudaEventDisableTiming);
        cudaEventCreateWithFlags(&evPB, cudaEventDisableTiming);
        for (int i = 0; i < NSEGD; i++)
            cudaEventCreateWithFlags(&evL[i], cudaEventDisableTiming);
        cudaFuncSetAttribute(gemm_tc<0>, cudaFuncAttributeMaxDynamicSharedMemorySize, GEMM_SMEM);
        cudaFuncSetAttribute(gemm_tc<1>, cudaFuncAttributeMaxDynamicSharedMemorySize, GEMM_SMEM);
    }

    // ---- stream 0: prep + encoder ----
    prep_k<<<(P_W2 + 255) / 256, 256>>>(enc_Wih, dec_Wih, pre_W, post_W1, stop_W1, post_W2,
                                        post_b1, stop_b1);
    gather_emb<<<M_ENC, 256>>>(token_pad, emb, pTE);
    cudaEventRecord(evR, 0);
    gemm_tc<0><<<dim3(M_ENC/128, G4/256), 256, GEMM_SMEM>>>(pTE, 256, 0, M_ENC, 256,
        pWr + W_ENC, 256, enc_bih, enc_bhh, pXencG, M_ENC, G4, 256, 1, 0, 0, nullptr, nullptr);
    lstm_enc_k<<<SEQ_NB, SEQ_NT>>>(enc_Whh, token_lengths);

    // ---- s1/s1b: 2-stage prenet / dec-gate software pipeline ----
    cudaStreamWaitEvent(s1, evR, 0);
    cvec_k<<<G4/8, 256, 0, s1>>>(pre_b, dec_bih, dec_bhh);
    const int HALF = 25600;
    // prenet chunk A (rows 0..HALF)
    gemm_tc<1><<<dim3(HALF/128, 1), 256, GEMM_SMEM, s1>>>(
        S_true, D_S, 64, HALF, D_S,
        pWr + W_PRE, KP_S, pre_b, nullptr, pXd, HALF, D_H, KP_S, 0, 0, 1, nullptr, nullptr);
    cudaEventRecord(evPA, s1);
    // prenet chunk B (rows HALF..M_VAL)
    gemm_tc<1><<<dim3((M_VAL-HALF)/128, 1), 256, GEMM_SMEM, s1>>>(
        S_true + (size_t)HALF * D_S, D_S, 0, M_VAL - HALF, D_S,
        pWr + W_PRE, KP_S, pre_b, nullptr, pXd + (size_t)HALF * D_H,
        M_VAL - HALF, D_H, KP_S, 0, 0, 1, nullptr, nullptr);
    cudaEventRecord(evPB, s1);
    // dec-gate chunk A on s1b (overlaps prenet B)
    cudaStreamWaitEvent(s1b, evPA, 0);
    gemm_tc<0><<<dim3(HALF/128, G4/256), 256, GEMM_SMEM, s1b>>>(
        pXd, 256, 0, HALF, 256,
        pWr + W_DEC, 256, dec_bih, dec_bhh, pXdG, HALF, G4, 256, 1, 0, 0, nullptr, nullptr);
    // dec-gate chunk B
    cudaStreamWaitEvent(s1b, evPB, 0);
    gemm_tc<0><<<dim3((M_VAL-HALF)/128, G4/256), 256, GEMM_SMEM, s1b>>>(
        pXd + (size_t)HALF * D_H, 256, 0, M_VAL - HALF, 256,
        pWr + W_DEC, 256, dec_bih, dec_bhh, pXdG + (size_t)HALF * G4,
        M_VAL - HALF, G4, 256, 1, 0, 0, nullptr, nullptr);
    cudaEventRecord(evD, s1b);

    // ---- stream 0: decoder recurrence in 10 segments (starts after ALL gates) ----
    cudaStreamWaitEvent(0, evD, 0);
    for (int i = 0; i < NSEGD; i++) {
        lstm_dec_k<<<SEQ_NB, SEQ_NT>>>(dec_Whh, LT + i * SEG_STEPS, LT + (i + 1) * SEG_STEPS);
        cudaEventRecord(evL[i], 0);
    }

    // ---- s2: per-segment post-net chunks overlap the decoder recurrence ----
    for (int i = 0; i < NSEGD; i++) {
        cudaStreamWaitEvent(s2, evL[i], 0);
        const float* Hc  = pH   + (size_t)SEG_ROWS * i * 256;
        float*       Hic = pHid + (size_t)SEG_ROWS * i * 256;
        gemm_tc<0><<<dim3(SEG_ROWS/128, 2), 256, GEMM_SMEM, s2>>>(Hc, 256, 0, SEG_ROWS, 256,
            pWr + W_P1S, 256, pBcat, nullptr, Hic, SEG_ROWS, 512, 256, 2, 1, 1,
            stop_W2, pStopP + (size_t)SEG_ROWS * i);
        gemm_tc<0><<<dim3(SEG_ROWS/128, 3), 256, GEMM_SMEM, s2>>>(Hic, 256, 0, SEG_ROWS, 256,
            pWr + W_POST2, 256, post_b2, nullptr, out + (size_t)SEG_ROWS * i * D_S,
            SEG_ROWS, D_S, 256, 0, 0, 0, nullptr, nullptr);
    }
    stopfin_k<<<(M_DEC+255)/256, 256, 0, s2>>>(stop_b2, out + STOP_OFF);
    cudaEventRecord(evJ, s2);

    cudaStreamWaitEvent(0, evJ, 0);
}